// round 8
// baseline (speedup 1.0000x reference)
#include <cuda_runtime.h>
#include <cuda_bf16.h>
#include <math.h>
#include <stdint.h>

#define NB 4
#define NT 2048
#define ND 1024
#define NH 16
#define NHD 64

// ---------------------------------------------------------------------------
// scratch (allocation-free rule: __device__ globals)
// ---------------------------------------------------------------------------
__device__ __align__(256) __nv_bfloat16 g_x_hi[(size_t)NB * NT * ND];
__device__ __align__(256) __nv_bfloat16 g_x_lo[(size_t)NB * NT * ND];
__device__ __align__(256) __nv_bfloat16 g_wq_hi[(size_t)3 * ND * ND];      // Wqkv^T [3D, D]
__device__ __align__(256) __nv_bfloat16 g_wq_lo[(size_t)3 * ND * ND];
__device__ __align__(256) __nv_bfloat16 g_wo_hi[(size_t)ND * ND];          // Wout^T [D, D]
__device__ __align__(256) __nv_bfloat16 g_wo_lo[(size_t)ND * ND];
__device__ __align__(256) __nv_bfloat16 g_att_hi[(size_t)NB * NT * ND];
__device__ __align__(256) __nv_bfloat16 g_att_lo[(size_t)NB * NT * ND];
// per-head split q/k/v: [B,H,T,64] bf16 (written by QKV GEMM epilogue)
__device__ __align__(256) __nv_bfloat16 g_q_hi[(size_t)NB * NH * NT * NHD];
__device__ __align__(256) __nv_bfloat16 g_q_lo[(size_t)NB * NH * NT * NHD];
__device__ __align__(256) __nv_bfloat16 g_k_hi[(size_t)NB * NH * NT * NHD];
__device__ __align__(256) __nv_bfloat16 g_k_lo[(size_t)NB * NH * NT * NHD];
__device__ __align__(256) __nv_bfloat16 g_v_hi[(size_t)NB * NH * NT * NHD];
__device__ __align__(256) __nv_bfloat16 g_v_lo[(size_t)NB * NH * NT * NHD];
// entity bias in bf16
__device__ __align__(256) __nv_bfloat16 g_eb_bf[(size_t)NB * NT * NT];

// ---------------------------------------------------------------------------
// PTX helpers (all baseline sm_80+)
// ---------------------------------------------------------------------------
__device__ __forceinline__ uint32_t smem_u32(const void* p) {
    uint32_t a;
    asm("{ .reg .u64 t; cvta.to.shared.u64 t, %1; cvt.u32.u64 %0, t; }" : "=r"(a) : "l"(p));
    return a;
}
__device__ __forceinline__ void ldsm4(uint32_t* r, uint32_t addr) {
    asm volatile("ldmatrix.sync.aligned.m8n8.x4.shared.b16 {%0,%1,%2,%3}, [%4];"
                 : "=r"(r[0]), "=r"(r[1]), "=r"(r[2]), "=r"(r[3]) : "r"(addr));
}
__device__ __forceinline__ void ldsm4t(uint32_t* r, uint32_t addr) {
    asm volatile("ldmatrix.sync.aligned.m8n8.x4.trans.shared.b16 {%0,%1,%2,%3}, [%4];"
                 : "=r"(r[0]), "=r"(r[1]), "=r"(r[2]), "=r"(r[3]) : "r"(addr));
}
__device__ __forceinline__ void mma_bf16(float* c, const uint32_t* a, const uint32_t* b) {
    asm volatile(
        "mma.sync.aligned.m16n8k16.row.col.f32.bf16.bf16.f32 "
        "{%0,%1,%2,%3}, {%4,%5,%6,%7}, {%8,%9}, {%0,%1,%2,%3};"
        : "+f"(c[0]), "+f"(c[1]), "+f"(c[2]), "+f"(c[3])
        : "r"(a[0]), "r"(a[1]), "r"(a[2]), "r"(a[3]), "r"(b[0]), "r"(b[1]));
}
__device__ __forceinline__ void cp16(uint32_t smem, const void* g) {
    asm volatile("cp.async.cg.shared.global [%0], [%1], 16;" :: "r"(smem), "l"(g));
}
#define CP_COMMIT() asm volatile("cp.async.commit_group;" ::: "memory")
#define CP_WAIT1()  asm volatile("cp.async.wait_group 1;" ::: "memory")
#define CP_WAIT0()  asm volatile("cp.async.wait_group 0;" ::: "memory")

__device__ __forceinline__ uint32_t packbf(float a, float b) {
    __nv_bfloat162 t = __float22bfloat162_rn(make_float2(a, b));
    return *reinterpret_cast<uint32_t*>(&t);
}
__device__ __forceinline__ uint32_t packlo(float a, float b, uint32_t hi) {
    __nv_bfloat162 h = *reinterpret_cast<__nv_bfloat162*>(&hi);
    float2 hf = __bfloat1622float2(h);
    return packbf(a - hf.x, b - hf.y);
}

// ---------------------------------------------------------------------------
// prepasses
// ---------------------------------------------------------------------------
__global__ __launch_bounds__(256)
void split_kernel(const float* __restrict__ src, __nv_bfloat16* __restrict__ hi,
                  __nv_bfloat16* __restrict__ lo, int n)
{
    int i = blockIdx.x * 256 + threadIdx.x;
    if (i < n) {
        float v = src[i];
        __nv_bfloat16 h = __float2bfloat16(v);
        hi[i] = h;
        lo[i] = __float2bfloat16(v - __bfloat162float(h));
    }
}

__global__ __launch_bounds__(256)
void bias_to_bf16_kernel(const float* __restrict__ src, __nv_bfloat16* __restrict__ dst)
{
    const size_t i = ((size_t)blockIdx.x * 256 + threadIdx.x) * 4;
    const float4 v = *reinterpret_cast<const float4*>(src + i);
    uint32_t p0 = packbf(v.x, v.y);
    uint32_t p1 = packbf(v.z, v.w);
    *reinterpret_cast<uint32_t*>(dst + i)     = p0;
    *reinterpret_cast<uint32_t*>(dst + i + 2) = p1;
}

__global__ __launch_bounds__(256)
void transpose_split_kernel(const float* __restrict__ W, __nv_bfloat16* __restrict__ Thi,
                            __nv_bfloat16* __restrict__ Tlo, int K, int N)
{
    __shared__ float t[32][33];
    const int n0 = blockIdx.x * 32, k0 = blockIdx.y * 32;
    const int tx = threadIdx.x, ty = threadIdx.y;   // 32 x 8
    #pragma unroll
    for (int j = 0; j < 32; j += 8)
        t[ty + j][tx] = W[(size_t)(k0 + ty + j) * N + n0 + tx];
    __syncthreads();
    #pragma unroll
    for (int j = 0; j < 32; j += 8) {
        float v = t[tx][ty + j];
        __nv_bfloat16 h = __float2bfloat16(v);
        size_t o = (size_t)(n0 + ty + j) * K + k0 + tx;
        Thi[o] = h;
        Tlo[o] = __float2bfloat16(v - __bfloat162float(h));
    }
}

// ---------------------------------------------------------------------------
// mma.sync bf16x3 GEMM (unchanged, proven): 2-stage pipeline, 2 CTAs/SM.
// ---------------------------------------------------------------------------
#define STG_BYTES 40960
#define T_AHI 0
#define T_ALO 10240
#define T_BHI 20480
#define T_BLO 30720

template <int MODE>
__global__ __launch_bounds__(256, 2)
void gemm_bf16x3(const __nv_bfloat16* __restrict__ Ahi, const __nv_bfloat16* __restrict__ Alo,
                 const __nv_bfloat16* __restrict__ Bhi, const __nv_bfloat16* __restrict__ Blo,
                 const float* __restrict__ bias, float* __restrict__ C,
                 __nv_bfloat16* __restrict__ qhi, __nv_bfloat16* __restrict__ qlo,
                 __nv_bfloat16* __restrict__ khi, __nv_bfloat16* __restrict__ klo,
                 __nv_bfloat16* __restrict__ vhi, __nv_bfloat16* __restrict__ vlo,
                 int M, int N, int K)
{
    extern __shared__ char dynsm[];
    const uint32_t sb0 = smem_u32(dynsm);

    const int tid = threadIdx.x;
    const int wid = tid >> 5;
    const int l   = tid & 31;
    const int wm  = wid >> 1;
    const int wn  = wid & 1;
    const size_t m0 = (size_t)blockIdx.y * 128;
    const size_t n0 = (size_t)blockIdx.x * 128;

    const int r1 = tid >> 2;
    const int r2 = r1 + 64;
    const int cc = (tid & 3);
    const uint32_t sm_off1 = (uint32_t)r1 * 80 + cc * 16;
    const uint32_t sm_off2 = (uint32_t)r2 * 80 + cc * 16;

    const int nchunks = K >> 5;

    auto issue_stage = [&](int c, int buf) {
        const int kc = c << 5;
        const uint32_t sb = sb0 + buf * STG_BYTES;
        cp16(sb + T_AHI + sm_off1, Ahi + (m0 + r1) * K + kc + cc * 8);
        cp16(sb + T_AHI + sm_off2, Ahi + (m0 + r2) * K + kc + cc * 8);
        cp16(sb + T_ALO + sm_off1, Alo + (m0 + r1) * K + kc + cc * 8);
        cp16(sb + T_ALO + sm_off2, Alo + (m0 + r2) * K + kc + cc * 8);
        cp16(sb + T_BHI + sm_off1, Bhi + (n0 + r1) * K + kc + cc * 8);
        cp16(sb + T_BHI + sm_off2, Bhi + (n0 + r2) * K + kc + cc * 8);
        cp16(sb + T_BLO + sm_off1, Blo + (n0 + r1) * K + kc + cc * 8);
        cp16(sb + T_BLO + sm_off2, Blo + (n0 + r2) * K + kc + cc * 8);
        CP_COMMIT();
    };

    const int aRow = (l & 7) + ((l >> 3) & 1) * 8;
    const int aCol8 = (l >> 4) * 8;
    const int bRow = (l & 7) + ((l >> 4) & 1) * 8;
    const int bCol8 = ((l >> 3) & 1) * 8;

    float acc[2][8][4];
    #pragma unroll
    for (int mt = 0; mt < 2; mt++)
        #pragma unroll
        for (int nt = 0; nt < 8; nt++)
            #pragma unroll
            for (int k = 0; k < 4; k++) acc[mt][nt][k] = 0.f;

    issue_stage(0, 0);

    for (int c = 0; c < nchunks; c++) {
        if (c + 1 < nchunks) {
            issue_stage(c + 1, (c + 1) & 1);
            CP_WAIT1();
        } else {
            CP_WAIT0();
        }
        __syncthreads();

        const uint32_t sb = sb0 + (c & 1) * STG_BYTES;
        const uint32_t aBase = sb + (uint32_t)(wm * 32 + aRow) * 80 + aCol8 * 2;
        const uint32_t bBase = sb + (uint32_t)(wn * 64 + bRow) * 80 + bCol8 * 2;

        #pragma unroll
        for (int ks = 0; ks < 2; ks++) {
            uint32_t ah[2][4], al4[2][4];
            #pragma unroll
            for (int mt = 0; mt < 2; mt++) {
                ldsm4(ah[mt],  aBase + T_AHI + mt * (16 * 80) + ks * 32);
                ldsm4(al4[mt], aBase + T_ALO + mt * (16 * 80) + ks * 32);
            }
            #pragma unroll
            for (int np = 0; np < 4; np++) {
                uint32_t bh[4], bl4[4];
                ldsm4(bh,  bBase + T_BHI + np * (16 * 80) + ks * 32);
                ldsm4(bl4, bBase + T_BLO + np * (16 * 80) + ks * 32);
                #pragma unroll
                for (int mt = 0; mt < 2; mt++)
                    #pragma unroll
                    for (int sub = 0; sub < 2; sub++) {
                        const int nt = np * 2 + sub;
                        mma_bf16(acc[mt][nt], ah[mt],  &bh[sub * 2]);
                        mma_bf16(acc[mt][nt], ah[mt],  &bl4[sub * 2]);
                        mma_bf16(acc[mt][nt], al4[mt], &bh[sub * 2]);
                    }
            }
        }
        __syncthreads();
    }

    if (MODE == 0) {
        #pragma unroll
        for (int mt = 0; mt < 2; mt++) {
            const size_t row0 = m0 + wm * 32 + mt * 16 + (l >> 2);
            #pragma unroll
            for (int nt = 0; nt < 8; nt++) {
                const size_t col = n0 + wn * 64 + nt * 8 + (l & 3) * 2;
                const float b0 = bias[col], b1 = bias[col + 1];
                float2 v0 = { acc[mt][nt][0] + b0, acc[mt][nt][1] + b1 };
                float2 v1 = { acc[mt][nt][2] + b0, acc[mt][nt][3] + b1 };
                *reinterpret_cast<float2*>(&C[row0 * N + col]) = v0;
                *reinterpret_cast<float2*>(&C[(row0 + 8) * N + col]) = v1;
            }
        }
    } else {
        const int colbase = (int)n0 + wn * 64;
        const int sel = colbase >> 10;
        const int head = (colbase >> 6) & 15;
        __nv_bfloat16* dh = (sel == 0) ? qhi : (sel == 1) ? khi : vhi;
        __nv_bfloat16* dl = (sel == 0) ? qlo : (sel == 1) ? klo : vlo;
        #pragma unroll
        for (int mt = 0; mt < 2; mt++) {
            const int row0 = (int)m0 + wm * 32 + mt * 16 + (l >> 2);
            const int bb = row0 >> 11;
            const int t0 = row0 & 2047;
            const size_t base = ((size_t)(bb * NH + head) * NT + t0) * NHD;
            #pragma unroll
            for (int nt = 0; nt < 8; nt++) {
                const int col = colbase + nt * 8 + (l & 3) * 2;
                const int d = col & 63;
                const float b0 = bias[col], b1 = bias[col + 1];
                const float v0 = acc[mt][nt][0] + b0, v1 = acc[mt][nt][1] + b1;
                const float v2 = acc[mt][nt][2] + b0, v3 = acc[mt][nt][3] + b1;
                const uint32_t h0 = packbf(v0, v1), lo0 = packlo(v0, v1, h0);
                const uint32_t h1 = packbf(v2, v3), lo1 = packlo(v2, v3, h1);
                *reinterpret_cast<uint32_t*>(dh + base + d)            = h0;
                *reinterpret_cast<uint32_t*>(dl + base + d)            = lo0;
                *reinterpret_cast<uint32_t*>(dh + base + 8 * NHD + d)  = h1;
                *reinterpret_cast<uint32_t*>(dl + base + 8 * NHD + d)  = lo1;
            }
        }
    }
}

// ---------------------------------------------------------------------------
// Tensor-core flash attention, keytile 64, 2 CTAs/SM, low-register variant:
//  - Q (hi/lo) persists in a dedicated smem region; fragments reloaded per tile
//  - entity bias read by direct LDG from bf16 array (L2-resident), no smem/sync
//  - exactly ONE __syncthreads per tile
// smem: 2 x 36864 KV double buffer + 36864 Q = 110592 B  -> 2 CTAs/SM.
// ---------------------------------------------------------------------------
#define FROWB 144
#define KVARR64 (64 * FROWB)          // 9216
#define KVBUF64 (4 * KVARR64)         // 36864 : Khi|Klo|Vhi|Vlo
#define QOFF (2 * KVBUF64)            // 73728
#define QARR (128 * FROWB)            // 18432
#define FLASH_SMEM (QOFF + 2 * QARR)  // 110592

__global__ __launch_bounds__(256, 2)
void flash_mma(const __nv_bfloat16* __restrict__ qhi, const __nv_bfloat16* __restrict__ qlo,
               const __nv_bfloat16* __restrict__ khi, const __nv_bfloat16* __restrict__ klo,
               const __nv_bfloat16* __restrict__ vhi, const __nv_bfloat16* __restrict__ vlo,
               const __nv_bfloat16* __restrict__ ebias,
               __nv_bfloat16* __restrict__ out_hi, __nv_bfloat16* __restrict__ out_lo)
{
    extern __shared__ char sm[];
    const uint32_t s0 = smem_u32(sm);
    const int tid = threadIdx.x, w = tid >> 5, l = tid & 31;
    const int qb = 15 - blockIdx.x;          // heavy CTAs first
    const int h = blockIdx.y, b = blockIdx.z;
    const int q0 = qb * 128;
    const size_t hoff = (size_t)(b * NH + h) * NT * NHD;
    const int ntiles = 2 * qb + 2;           // key tiles of 64

    auto issue_kv = [&](int jt2, int bsel2) {
        #pragma unroll
        for (int i = 0; i < 8; i++) {
            const int ck = tid + i * 256;            // 0..2047
            const int arr = ck >> 9;                 // 0..3
            const int row = (ck >> 3) & 63;
            const int seg = ck & 7;
            const size_t go = hoff + (size_t)(jt2 * 64 + row) * NHD + seg * 8;
            const __nv_bfloat16* src = (arr == 0) ? khi + go : (arr == 1) ? klo + go
                                      : (arr == 2) ? vhi + go : vlo + go;
            cp16(s0 + bsel2 * KVBUF64 + arr * KVARR64 + row * FROWB + seg * 16, src);
        }
        CP_COMMIT();
    };

    // prologue: Q (128 rows hi+lo) -> persistent region, KV(0) -> buf0
    #pragma unroll
    for (int i = 0; i < 8; i++) {
        const int cq = tid + i * 256;                // 0..2047
        const int arr = cq >> 10;                    // 0=hi,1=lo
        const int row = (cq >> 3) & 127;
        const int seg = cq & 7;
        const __nv_bfloat16* src = (arr ? qlo : qhi) + hoff + (size_t)(q0 + row) * NHD + seg * 8;
        cp16(s0 + QOFF + arr * QARR + row * FROWB + seg * 16, src);
    }
    CP_COMMIT();
    issue_kv(0, 0);

    float O[8][4];
    #pragma unroll
    for (int nt = 0; nt < 8; nt++)
        #pragma unroll
        for (int k = 0; k < 4; k++) O[nt][k] = 0.f;
    float m0 = -INFINITY, m1 = -INFINITY, l0 = 0.f, l1 = 0.f;

    const int r0 = w * 16 + (l >> 2), r1 = r0 + 8;
    const int gq0 = q0 + r0, gq1 = q0 + r1;
    const uint32_t nRow = (uint32_t)((l & 7) + ((l >> 4) & 1) * 8);
    const uint32_t kColB = (uint32_t)(((l >> 3) & 1) * 16);
    const uint32_t vRowP = (uint32_t)((l & 7) + ((l >> 3) & 1) * 8);
    const uint32_t vColB = (uint32_t)(((l >> 4) & 1) * 16);
    const uint32_t qbase = s0 + QOFF +
        (uint32_t)(w * 16 + (l & 7) + ((l >> 3) & 1) * 8) * FROWB + ((l >> 4) * 16);
    // bias row pointers (bf16, L2-resident); per-thread column base
    const __nv_bfloat16* bias0 = ebias + ((size_t)b * NT + gq0) * NT + 2 * (l & 3);
    const __nv_bfloat16* bias1 = ebias + ((size_t)b * NT + gq1) * NT + 2 * (l & 3);

    for (int jt = 0; jt < ntiles; jt++) {
        const int bsel = jt & 1;
        CP_WAIT0();
        __syncthreads();                 // KV(jt) ready; all warps done with buf (jt+1)&1
        if (jt + 1 < ntiles) issue_kv(jt + 1, bsel ^ 1);

        // prefetch bias for this tile into registers (hidden under QK MMAs)
        uint32_t breg[16];
        #pragma unroll
        for (int nt = 0; nt < 8; nt++) {
            breg[nt]     = *reinterpret_cast<const uint32_t*>(bias0 + jt * 64 + nt * 8);
            breg[8 + nt] = *reinterpret_cast<const uint32_t*>(bias1 + jt * 64 + nt * 8);
        }

        // ---- S = Q K^T (bf16x3) over 64 keys
        float acc[8][4];
        #pragma unroll
        for (int nt = 0; nt < 8; nt++)
            #pragma unroll
            for (int k = 0; k < 4; k++) acc[nt][k] = 0.f;

        const uint32_t kb = s0 + bsel * KVBUF64;
        #pragma unroll
        for (int ks = 0; ks < 4; ks++) {
            uint32_t qhf[4], qlf[4];
            ldsm4(qhf, qbase + ks * 32);
            ldsm4(qlf, qbase + QARR + ks * 32);
            #pragma unroll
            for (int np = 0; np < 4; np++) {
                uint32_t khf[4], klf[4];
                const uint32_t a = kb + (np * 16 + nRow) * FROWB + kColB + ks * 32;
                ldsm4(khf, a);
                ldsm4(klf, a + KVARR64);
                #pragma unroll
                for (int sub = 0; sub < 2; sub++) {
                    const int nt = np * 2 + sub;
                    mma_bf16(acc[nt], qhf, &khf[sub * 2]);
                    mma_bf16(acc[nt], qhf, &klf[sub * 2]);
                    mma_bf16(acc[nt], qlf, &khf[sub * 2]);
                }
            }
        }

        // ---- scale + bias (regs) + causal mask + online softmax
        float mx0 = -INFINITY, mx1 = -INFINITY;
        const bool masktile = (jt >= 2 * qb);       // last two tiles touch diagonal
        #pragma unroll
        for (int nt = 0; nt < 8; nt++) {
            float2 bv0 = __bfloat1622float2(*reinterpret_cast<__nv_bfloat162*>(&breg[nt]));
            float2 bv1 = __bfloat1622float2(*reinterpret_cast<__nv_bfloat162*>(&breg[8 + nt]));
            float v0 = acc[nt][0] * 0.125f + bv0.x;
            float v1 = acc[nt][1] * 0.125f + bv0.y;
            float v2 = acc[nt][2] * 0.125f + bv1.x;
            float v3 = acc[nt][3] * 0.125f + bv1.y;
            if (masktile) {
                const int kc = jt * 64 + nt * 8 + 2 * (l & 3);
                if (kc > gq0)     v0 = -1e30f;
                if (kc + 1 > gq0) v1 = -1e30f;
                if (kc > gq1)     v2 = -1e30f;
                if (kc + 1 > gq1) v3 = -1e30f;
            }
            acc[nt][0] = v0; acc[nt][1] = v1; acc[nt][2] = v2; acc[nt][3] = v3;
            mx0 = fmaxf(mx0, fmaxf(v0, v1));
            mx1 = fmaxf(mx1, fmaxf(v2, v3));
        }
        mx0 = fmaxf(mx0, __shfl_xor_sync(0xffffffff, mx0, 1));
        mx0 = fmaxf(mx0, __shfl_xor_sync(0xffffffff, mx0, 2));
        mx1 = fmaxf(mx1, __shfl_xor_sync(0xffffffff, mx1, 1));
        mx1 = fmaxf(mx1, __shfl_xor_sync(0xffffffff, mx1, 2));

        const float mn0 = fmaxf(m0, mx0), mn1 = fmaxf(m1, mx1);
        const float c0 = __expf(m0 - mn0), c1 = __expf(m1 - mn1);
        float rs0 = 0.f, rs1 = 0.f;
        #pragma unroll
        for (int nt = 0; nt < 8; nt++) {
            const float p0 = __expf(acc[nt][0] - mn0);
            const float p1 = __expf(acc[nt][1] - mn0);
            const float p2 = __expf(acc[nt][2] - mn1);
            const float p3 = __expf(acc[nt][3] - mn1);
            acc[nt][0] = p0; acc[nt][1] = p1; acc[nt][2] = p2; acc[nt][3] = p3;
            rs0 += p0 + p1;
            rs1 += p2 + p3;
        }
        rs0 += __shfl_xor_sync(0xffffffff, rs0, 1);
        rs0 += __shfl_xor_sync(0xffffffff, rs0, 2);
        rs1 += __shfl_xor_sync(0xffffffff, rs1, 1);
        rs1 += __shfl_xor_sync(0xffffffff, rs1, 2);
        l0 = l0 * c0 + rs0;
        l1 = l1 * c1 + rs1;
        m0 = mn0; m1 = mn1;
        #pragma unroll
        for (int nt = 0; nt < 8; nt++) {
            O[nt][0] *= c0; O[nt][1] *= c0; O[nt][2] *= c1; O[nt][3] *= c1;
        }

        // ---- O += P V (bf16x3) over 64 keys (same buffer as QK; no extra sync)
        const uint32_t vb = kb + 2 * KVARR64;
        #pragma unroll
        for (int kk = 0; kk < 4; kk++) {
            uint32_t phi[4], plo[4];
            phi[0] = packbf(acc[2 * kk][0], acc[2 * kk][1]);
            plo[0] = packlo(acc[2 * kk][0], acc[2 * kk][1], phi[0]);
            phi[1] = packbf(acc[2 * kk][2], acc[2 * kk][3]);
            plo[1] = packlo(acc[2 * kk][2], acc[2 * kk][3], phi[1]);
            phi[2] = packbf(acc[2 * kk + 1][0], acc[2 * kk + 1][1]);
            plo[2] = packlo(acc[2 * kk + 1][0], acc[2 * kk + 1][1], phi[2]);
            phi[3] = packbf(acc[2 * kk + 1][2], acc[2 * kk + 1][3]);
            plo[3] = packlo(acc[2 * kk + 1][2], acc[2 * kk + 1][3], phi[3]);
            #pragma unroll
            for (int nn = 0; nn < 4; nn++) {
                uint32_t vhf[4], vlf[4];
                const uint32_t va = vb + (kk * 16 + vRowP) * FROWB + nn * 32 + vColB;
                ldsm4t(vhf, va);
                ldsm4t(vlf, va + KVARR64);
                #pragma unroll
                for (int sub = 0; sub < 2; sub++) {
                    const int nt = nn * 2 + sub;
                    mma_bf16(O[nt], phi, &vhf[sub * 2]);
                    mma_bf16(O[nt], phi, &vlf[sub * 2]);
                    mma_bf16(O[nt], plo, &vhf[sub * 2]);
                }
            }
        }
    }

    // ---- epilogue: O/l -> bf16 hi/lo, [B,T,D] layout
    const float inv0 = 1.f / l0, inv1 = 1.f / l1;
    const size_t a0 = ((size_t)b * NT + gq0) * ND + h * NHD + 2 * (l & 3);
    const size_t a1 = ((size_t)b * NT + gq1) * ND + h * NHD + 2 * (l & 3);
    #pragma unroll
    for (int nt = 0; nt < 8; nt++) {
        const float o0 = O[nt][0] * inv0, o1 = O[nt][1] * inv0;
        const float o2 = O[nt][2] * inv1, o3 = O[nt][3] * inv1;
        const uint32_t h0 = packbf(o0, o1), lo0 = packlo(o0, o1, h0);
        const uint32_t h1 = packbf(o2, o3), lo1 = packlo(o2, o3, h1);
        *reinterpret_cast<uint32_t*>(out_hi + a0 + nt * 8) = h0;
        *reinterpret_cast<uint32_t*>(out_lo + a0 + nt * 8) = lo0;
        *reinterpret_cast<uint32_t*>(out_hi + a1 + nt * 8) = h1;
        *reinterpret_cast<uint32_t*>(out_lo + a1 + nt * 8) = lo1;
    }
}

// ---------------------------------------------------------------------------
extern "C" void kernel_launch(void* const* d_in, const int* in_sizes, int n_in,
                              void* d_out, int out_size)
{
    const float* x     = (const float*)d_in[0];
    const float* eb    = (const float*)d_in[1];
    const float* Wqkv  = (const float*)d_in[2];
    const float* bqkv  = (const float*)d_in[3];
    const float* Wout  = (const float*)d_in[4];
    const float* bout  = (const float*)d_in[5];
    float* out = (float*)d_out;

    __nv_bfloat16 *xhi, *xlo, *wqhi, *wqlo, *wohi, *wolo, *athi, *atlo;
    __nv_bfloat16 *qhi, *qlo, *khi2, *klo2, *vhi2, *vlo2, *ebbf;
    cudaGetSymbolAddress((void**)&xhi,  g_x_hi);
    cudaGetSymbolAddress((void**)&xlo,  g_x_lo);
    cudaGetSymbolAddress((void**)&wqhi, g_wq_hi);
    cudaGetSymbolAddress((void**)&wqlo, g_wq_lo);
    cudaGetSymbolAddress((void**)&wohi, g_wo_hi);
    cudaGetSymbolAddress((void**)&wolo, g_wo_lo);
    cudaGetSymbolAddress((void**)&athi, g_att_hi);
    cudaGetSymbolAddress((void**)&atlo, g_att_lo);
    cudaGetSymbolAddress((void**)&qhi,  g_q_hi);
    cudaGetSymbolAddress((void**)&qlo,  g_q_lo);
    cudaGetSymbolAddress((void**)&khi2, g_k_hi);
    cudaGetSymbolAddress((void**)&klo2, g_k_lo);
    cudaGetSymbolAddress((void**)&vhi2, g_v_hi);
    cudaGetSymbolAddress((void**)&vlo2, g_v_lo);
    cudaGetSymbolAddress((void**)&ebbf, g_eb_bf);

    const int M = NB * NT;   // 8192

    // 0) prepasses
    split_kernel<<<(M * ND + 255) / 256, 256>>>(x, xhi, xlo, M * ND);
    {
        dim3 blk(32, 8);
        transpose_split_kernel<<<dim3(3 * ND / 32, ND / 32), blk>>>(Wqkv, wqhi, wqlo, ND, 3 * ND);
        transpose_split_kernel<<<dim3(ND / 32, ND / 32), blk>>>(Wout, wohi, wolo, ND, ND);
    }
    bias_to_bf16_kernel<<<(int)(((size_t)NB * NT * NT) / 4 / 256), 256>>>(eb, ebbf);

    const int gemm_smem = 2 * STG_BYTES;   // 81920 -> 2 CTAs/SM
    cudaFuncSetAttribute(gemm_bf16x3<0>, cudaFuncAttributeMaxDynamicSharedMemorySize, gemm_smem);
    cudaFuncSetAttribute(gemm_bf16x3<1>, cudaFuncAttributeMaxDynamicSharedMemorySize, gemm_smem);

    // 1) QKV projection, fused per-head split epilogue
    gemm_bf16x3<1><<<dim3(3 * ND / 128, M / 128), 256, gemm_smem>>>(
        xhi, xlo, wqhi, wqlo, bqkv, nullptr,
        qhi, qlo, khi2, klo2, vhi2, vlo2, M, 3 * ND, ND);

    // 2) tensor-core flash attention (2 CTAs/SM, 1 sync/tile, bias via LDG)
    cudaFuncSetAttribute(flash_mma, cudaFuncAttributeMaxDynamicSharedMemorySize, FLASH_SMEM);
    flash_mma<<<dim3(NT / 128, NH, NB), 256, FLASH_SMEM>>>(
        qhi, qlo, khi2, klo2, vhi2, vlo2, ebbf, athi, atlo);

    // 3) output projection (fp32 out + bias)
    gemm_bf16x3<0><<<dim3(ND / 128, M / 128), 256, gemm_smem>>>(
        athi, atlo, wohi, wolo, bout, out,
        nullptr, nullptr, nullptr, nullptr, nullptr, nullptr, M, ND, ND);
}

// round 10
// speedup vs baseline: 1.0026x; 1.0026x over previous
#include <cuda_runtime.h>
#include <cuda_bf16.h>
#include <math.h>
#include <stdint.h>

#define NB 4
#define NT 2048
#define ND 1024
#define NH 16
#define NHD 64

#define QSCALE 0.1803368801111244f   // 0.125 * log2(e)
#define LOG2E  1.4426950408889634f

// ---------------------------------------------------------------------------
// scratch (allocation-free rule: __device__ globals)
// ---------------------------------------------------------------------------
__device__ __align__(256) __nv_bfloat16 g_x_hi[(size_t)NB * NT * ND];
__device__ __align__(256) __nv_bfloat16 g_x_lo[(size_t)NB * NT * ND];
__device__ __align__(256) __nv_bfloat16 g_wq_hi[(size_t)3 * ND * ND];      // Wqkv^T [3D, D]
__device__ __align__(256) __nv_bfloat16 g_wq_lo[(size_t)3 * ND * ND];
__device__ __align__(256) __nv_bfloat16 g_wo_hi[(size_t)ND * ND];          // Wout^T [D, D]
__device__ __align__(256) __nv_bfloat16 g_wo_lo[(size_t)ND * ND];
__device__ __align__(256) __nv_bfloat16 g_att_hi[(size_t)NB * NT * ND];
__device__ __align__(256) __nv_bfloat16 g_att_lo[(size_t)NB * NT * ND];
// per-head split q/k/v: [B,H,T,64] bf16 (written by QKV GEMM epilogue; q pre-scaled)
__device__ __align__(256) __nv_bfloat16 g_q_hi[(size_t)NB * NH * NT * NHD];
__device__ __align__(256) __nv_bfloat16 g_q_lo[(size_t)NB * NH * NT * NHD];
__device__ __align__(256) __nv_bfloat16 g_k_hi[(size_t)NB * NH * NT * NHD];
__device__ __align__(256) __nv_bfloat16 g_k_lo[(size_t)NB * NH * NT * NHD];
__device__ __align__(256) __nv_bfloat16 g_v_hi[(size_t)NB * NH * NT * NHD];
__device__ __align__(256) __nv_bfloat16 g_v_lo[(size_t)NB * NH * NT * NHD];
// entity bias in bf16, pre-multiplied by log2(e)
__device__ __align__(256) __nv_bfloat16 g_eb_bf[(size_t)NB * NT * NT];

// ---------------------------------------------------------------------------
// PTX helpers (all baseline sm_80+)
// ---------------------------------------------------------------------------
__device__ __forceinline__ uint32_t smem_u32(const void* p) {
    uint32_t a;
    asm("{ .reg .u64 t; cvta.to.shared.u64 t, %1; cvt.u32.u64 %0, t; }" : "=r"(a) : "l"(p));
    return a;
}
__device__ __forceinline__ void ldsm4(uint32_t* r, uint32_t addr) {
    asm volatile("ldmatrix.sync.aligned.m8n8.x4.shared.b16 {%0,%1,%2,%3}, [%4];"
                 : "=r"(r[0]), "=r"(r[1]), "=r"(r[2]), "=r"(r[3]) : "r"(addr));
}
__device__ __forceinline__ void ldsm4t(uint32_t* r, uint32_t addr) {
    asm volatile("ldmatrix.sync.aligned.m8n8.x4.trans.shared.b16 {%0,%1,%2,%3}, [%4];"
                 : "=r"(r[0]), "=r"(r[1]), "=r"(r[2]), "=r"(r[3]) : "r"(addr));
}
__device__ __forceinline__ void mma_bf16(float* c, const uint32_t* a, const uint32_t* b) {
    asm volatile(
        "mma.sync.aligned.m16n8k16.row.col.f32.bf16.bf16.f32 "
        "{%0,%1,%2,%3}, {%4,%5,%6,%7}, {%8,%9}, {%0,%1,%2,%3};"
        : "+f"(c[0]), "+f"(c[1]), "+f"(c[2]), "+f"(c[3])
        : "r"(a[0]), "r"(a[1]), "r"(a[2]), "r"(a[3]), "r"(b[0]), "r"(b[1]));
}
__device__ __forceinline__ void cp16(uint32_t smem, const void* g) {
    asm volatile("cp.async.cg.shared.global [%0], [%1], 16;" :: "r"(smem), "l"(g));
}
#define CP_COMMIT() asm volatile("cp.async.commit_group;" ::: "memory")
#define CP_WAIT1()  asm volatile("cp.async.wait_group 1;" ::: "memory")
#define CP_WAIT0()  asm volatile("cp.async.wait_group 0;" ::: "memory")

__device__ __forceinline__ float fexp2(float x) {
    float r;
    asm("ex2.approx.f32 %0, %1;" : "=f"(r) : "f"(x));
    return r;
}
__device__ __forceinline__ uint32_t packbf(float a, float b) {
    __nv_bfloat162 t = __float22bfloat162_rn(make_float2(a, b));
    return *reinterpret_cast<uint32_t*>(&t);
}
__device__ __forceinline__ uint32_t packlo(float a, float b, uint32_t hi) {
    __nv_bfloat162 h = *reinterpret_cast<__nv_bfloat162*>(&hi);
    float2 hf = __bfloat1622float2(h);
    return packbf(a - hf.x, b - hf.y);
}

// ---------------------------------------------------------------------------
// fused prepass: ONE launch does x hi/lo split + both weight transpose-splits
// flat grid, branch on block range.  (launch index 0)
// ---------------------------------------------------------------------------
#define BLK_SPLIT 32768                       // 8M elems / 256
#define BLK_TQKV  3072                        // (3072/32)*(1024/32)
#define BLK_TWO   1024                        // (1024/32)*(1024/32)

__global__ __launch_bounds__(256)
void prepass_kernel(const float* __restrict__ x,
                    const float* __restrict__ Wqkv,
                    const float* __restrict__ Wout,
                    __nv_bfloat16* __restrict__ xhi, __nv_bfloat16* __restrict__ xlo,
                    __nv_bfloat16* __restrict__ wqhi, __nv_bfloat16* __restrict__ wqlo,
                    __nv_bfloat16* __restrict__ wohi, __nv_bfloat16* __restrict__ wolo)
{
    __shared__ float t[32][33];
    const int bid = blockIdx.x;
    const int tid = threadIdx.x;

    if (bid < BLK_SPLIT) {
        const int i = bid * 256 + tid;
        float v = x[i];
        __nv_bfloat16 h = __float2bfloat16(v);
        xhi[i] = h;
        xlo[i] = __float2bfloat16(v - __bfloat162float(h));
        return;
    }

    // transpose-split branch
    const float* W;
    __nv_bfloat16 *Thi, *Tlo;
    int N, tb;
    if (bid < BLK_SPLIT + BLK_TQKV) {
        tb = bid - BLK_SPLIT; W = Wqkv; Thi = wqhi; Tlo = wqlo; N = 3 * ND;
    } else {
        tb = bid - BLK_SPLIT - BLK_TQKV; W = Wout; Thi = wohi; Tlo = wolo; N = ND;
    }
    const int K = ND;
    const int n0 = (tb % (N / 32)) * 32;
    const int k0 = (tb / (N / 32)) * 32;
    const int tx = tid & 31, ty = tid >> 5;   // 32 x 8
    #pragma unroll
    for (int j = 0; j < 32; j += 8)
        t[ty + j][tx] = W[(size_t)(k0 + ty + j) * N + n0 + tx];
    __syncthreads();
    #pragma unroll
    for (int j = 0; j < 32; j += 8) {
        float v = t[tx][ty + j];
        __nv_bfloat16 h = __float2bfloat16(v);
        size_t o = (size_t)(n0 + ty + j) * K + k0 + tx;
        Thi[o] = h;
        Tlo[o] = __float2bfloat16(v - __bfloat162float(h));
    }
}

// ---------------------------------------------------------------------------
// entity bias fp32 -> bf16, pre-multiplied by log2(e)   (launch index 1)
// ---------------------------------------------------------------------------
__global__ __launch_bounds__(256)
void bias_to_bf16_kernel(const float* __restrict__ src, __nv_bfloat16* __restrict__ dst)
{
    const size_t i = ((size_t)blockIdx.x * 256 + threadIdx.x) * 4;
    const float4 v = *reinterpret_cast<const float4*>(src + i);
    uint32_t p0 = packbf(v.x * LOG2E, v.y * LOG2E);
    uint32_t p1 = packbf(v.z * LOG2E, v.w * LOG2E);
    *reinterpret_cast<uint32_t*>(dst + i)     = p0;
    *reinterpret_cast<uint32_t*>(dst + i + 2) = p1;
}

// ---------------------------------------------------------------------------
// mma.sync bf16x3 GEMM (proven): 2-stage pipeline, 2 CTAs/SM.
// MODE 1 scales q by QSCALE in the epilogue (logits emerge in log2 domain).
// ---------------------------------------------------------------------------
#define STG_BYTES 40960
#define T_AHI 0
#define T_ALO 10240
#define T_BHI 20480
#define T_BLO 30720

template <int MODE>
__global__ __launch_bounds__(256, 2)
void gemm_bf16x3(const __nv_bfloat16* __restrict__ Ahi, const __nv_bfloat16* __restrict__ Alo,
                 const __nv_bfloat16* __restrict__ Bhi, const __nv_bfloat16* __restrict__ Blo,
                 const float* __restrict__ bias, float* __restrict__ C,
                 __nv_bfloat16* __restrict__ qhi, __nv_bfloat16* __restrict__ qlo,
                 __nv_bfloat16* __restrict__ khi, __nv_bfloat16* __restrict__ klo,
                 __nv_bfloat16* __restrict__ vhi, __nv_bfloat16* __restrict__ vlo,
                 int M, int N, int K)
{
    extern __shared__ char dynsm[];
    const uint32_t sb0 = smem_u32(dynsm);

    const int tid = threadIdx.x;
    const int wid = tid >> 5;
    const int l   = tid & 31;
    const int wm  = wid >> 1;
    const int wn  = wid & 1;
    const size_t m0 = (size_t)blockIdx.y * 128;
    const size_t n0 = (size_t)blockIdx.x * 128;

    const int r1 = tid >> 2;
    const int r2 = r1 + 64;
    const int cc = (tid & 3);
    const uint32_t sm_off1 = (uint32_t)r1 * 80 + cc * 16;
    const uint32_t sm_off2 = (uint32_t)r2 * 80 + cc * 16;

    const int nchunks = K >> 5;

    auto issue_stage = [&](int c, int buf) {
        const int kc = c << 5;
        const uint32_t sb = sb0 + buf * STG_BYTES;
        cp16(sb + T_AHI + sm_off1, Ahi + (m0 + r1) * K + kc + cc * 8);
        cp16(sb + T_AHI + sm_off2, Ahi + (m0 + r2) * K + kc + cc * 8);
        cp16(sb + T_ALO + sm_off1, Alo + (m0 + r1) * K + kc + cc * 8);
        cp16(sb + T_ALO + sm_off2, Alo + (m0 + r2) * K + kc + cc * 8);
        cp16(sb + T_BHI + sm_off1, Bhi + (n0 + r1) * K + kc + cc * 8);
        cp16(sb + T_BHI + sm_off2, Bhi + (n0 + r2) * K + kc + cc * 8);
        cp16(sb + T_BLO + sm_off1, Blo + (n0 + r1) * K + kc + cc * 8);
        cp16(sb + T_BLO + sm_off2, Blo + (n0 + r2) * K + kc + cc * 8);
        CP_COMMIT();
    };

    const int aRow = (l & 7) + ((l >> 3) & 1) * 8;
    const int aCol8 = (l >> 4) * 8;
    const int bRow = (l & 7) + ((l >> 4) & 1) * 8;
    const int bCol8 = ((l >> 3) & 1) * 8;

    float acc[2][8][4];
    #pragma unroll
    for (int mt = 0; mt < 2; mt++)
        #pragma unroll
        for (int nt = 0; nt < 8; nt++)
            #pragma unroll
            for (int k = 0; k < 4; k++) acc[mt][nt][k] = 0.f;

    issue_stage(0, 0);

    for (int c = 0; c < nchunks; c++) {
        if (c + 1 < nchunks) {
            issue_stage(c + 1, (c + 1) & 1);
            CP_WAIT1();
        } else {
            CP_WAIT0();
        }
        __syncthreads();

        const uint32_t sb = sb0 + (c & 1) * STG_BYTES;
        const uint32_t aBase = sb + (uint32_t)(wm * 32 + aRow) * 80 + aCol8 * 2;
        const uint32_t bBase = sb + (uint32_t)(wn * 64 + bRow) * 80 + bCol8 * 2;

        #pragma unroll
        for (int ks = 0; ks < 2; ks++) {
            uint32_t ah[2][4], al4[2][4];
            #pragma unroll
            for (int mt = 0; mt < 2; mt++) {
                ldsm4(ah[mt],  aBase + T_AHI + mt * (16 * 80) + ks * 32);
                ldsm4(al4[mt], aBase + T_ALO + mt * (16 * 80) + ks * 32);
            }
            #pragma unroll
            for (int np = 0; np < 4; np++) {
                uint32_t bh[4], bl4[4];
                ldsm4(bh,  bBase + T_BHI + np * (16 * 80) + ks * 32);
                ldsm4(bl4, bBase + T_BLO + np * (16 * 80) + ks * 32);
                #pragma unroll
                for (int mt = 0; mt < 2; mt++)
                    #pragma unroll
                    for (int sub = 0; sub < 2; sub++) {
                        const int nt = np * 2 + sub;
                        mma_bf16(acc[mt][nt], ah[mt],  &bh[sub * 2]);
                        mma_bf16(acc[mt][nt], ah[mt],  &bl4[sub * 2]);
                        mma_bf16(acc[mt][nt], al4[mt], &bh[sub * 2]);
                    }
            }
        }
        __syncthreads();
    }

    if (MODE == 0) {
        #pragma unroll
        for (int mt = 0; mt < 2; mt++) {
            const size_t row0 = m0 + wm * 32 + mt * 16 + (l >> 2);
            #pragma unroll
            for (int nt = 0; nt < 8; nt++) {
                const size_t col = n0 + wn * 64 + nt * 8 + (l & 3) * 2;
                const float b0 = bias[col], b1 = bias[col + 1];
                float2 v0 = { acc[mt][nt][0] + b0, acc[mt][nt][1] + b1 };
                float2 v1 = { acc[mt][nt][2] + b0, acc[mt][nt][3] + b1 };
                *reinterpret_cast<float2*>(&C[row0 * N + col]) = v0;
                *reinterpret_cast<float2*>(&C[(row0 + 8) * N + col]) = v1;
            }
        }
    } else {
        const int colbase = (int)n0 + wn * 64;
        const int sel = colbase >> 10;
        const int head = (colbase >> 6) & 15;
        const float qs = (sel == 0) ? QSCALE : 1.0f;   // fold 0.125*log2e into q
        __nv_bfloat16* dh = (sel == 0) ? qhi : (sel == 1) ? khi : vhi;
        __nv_bfloat16* dl = (sel == 0) ? qlo : (sel == 1) ? klo : vlo;
        #pragma unroll
        for (int mt = 0; mt < 2; mt++) {
            const int row0 = (int)m0 + wm * 32 + mt * 16 + (l >> 2);
            const int bb = row0 >> 11;
            const int t0 = row0 & 2047;
            const size_t base = ((size_t)(bb * NH + head) * NT + t0) * NHD;
            #pragma unroll
            for (int nt = 0; nt < 8; nt++) {
                const int col = colbase + nt * 8 + (l & 3) * 2;
                const int d = col & 63;
                const float b0 = bias[col], b1 = bias[col + 1];
                const float v0 = (acc[mt][nt][0] + b0) * qs, v1 = (acc[mt][nt][1] + b1) * qs;
                const float v2 = (acc[mt][nt][2] + b0) * qs, v3 = (acc[mt][nt][3] + b1) * qs;
                const uint32_t h0 = packbf(v0, v1), lo0 = packlo(v0, v1, h0);
                const uint32_t h1 = packbf(v2, v3), lo1 = packlo(v2, v3, h1);
                *reinterpret_cast<uint32_t*>(dh + base + d)            = h0;
                *reinterpret_cast<uint32_t*>(dl + base + d)            = lo0;
                *reinterpret_cast<uint32_t*>(dh + base + 8 * NHD + d)  = h1;
                *reinterpret_cast<uint32_t*>(dl + base + 8 * NHD + d)  = lo1;
            }
        }
    }
}

// ---------------------------------------------------------------------------
// Tensor-core flash attention (log2-domain softmax), keytile 64, 2 CTAs/SM.
// q pre-scaled by 0.125*log2e; bias pre-scaled by log2e; exp via ex2.approx.
// smem: 2 x 36864 KV double buffer + 36864 Q = 110592 B.
// ---------------------------------------------------------------------------
#define FROWB 144
#define KVARR64 (64 * FROWB)          // 9216
#define KVBUF64 (4 * KVARR64)         // 36864 : Khi|Klo|Vhi|Vlo
#define QOFF (2 * KVBUF64)            // 73728
#define QARR (128 * FROWB)            // 18432
#define FLASH_SMEM (QOFF + 2 * QARR)  // 110592

__global__ __launch_bounds__(256, 2)
void flash_mma(const __nv_bfloat16* __restrict__ qhi, const __nv_bfloat16* __restrict__ qlo,
               const __nv_bfloat16* __restrict__ khi, const __nv_bfloat16* __restrict__ klo,
               const __nv_bfloat16* __restrict__ vhi, const __nv_bfloat16* __restrict__ vlo,
               const __nv_bfloat16* __restrict__ ebias,
               __nv_bfloat16* __restrict__ out_hi, __nv_bfloat16* __restrict__ out_lo)
{
    extern __shared__ char sm[];
    const uint32_t s0 = smem_u32(sm);
    const int tid = threadIdx.x, w = tid >> 5, l = tid & 31;
    const int qb = 15 - blockIdx.x;          // heavy CTAs first
    const int h = blockIdx.y, b = blockIdx.z;
    const int q0 = qb * 128;
    const size_t hoff = (size_t)(b * NH + h) * NT * NHD;
    const int ntiles = 2 * qb + 2;           // key tiles of 64

    auto issue_kv = [&](int jt2, int bsel2) {
        #pragma unroll
        for (int i = 0; i < 8; i++) {
            const int ck = tid + i * 256;            // 0..2047
            const int arr = ck >> 9;                 // 0..3
            const int row = (ck >> 3) & 63;
            const int seg = ck & 7;
            const size_t go = hoff + (size_t)(jt2 * 64 + row) * NHD + seg * 8;
            const __nv_bfloat16* src = (arr == 0) ? khi + go : (arr == 1) ? klo + go
                                      : (arr == 2) ? vhi + go : vlo + go;
            cp16(s0 + bsel2 * KVBUF64 + arr * KVARR64 + row * FROWB + seg * 16, src);
        }
        CP_COMMIT();
    };

    // prologue: Q (128 rows hi+lo) -> persistent region, KV(0) -> buf0
    #pragma unroll
    for (int i = 0; i < 8; i++) {
        const int cq = tid + i * 256;                // 0..2047
        const int arr = cq >> 10;                    // 0=hi,1=lo
        const int row = (cq >> 3) & 127;
        const int seg = cq & 7;
        const __nv_bfloat16* src = (arr ? qlo : qhi) + hoff + (size_t)(q0 + row) * NHD + seg * 8;
        cp16(s0 + QOFF + arr * QARR + row * FROWB + seg * 16, src);
    }
    CP_COMMIT();
    issue_kv(0, 0);

    float O[8][4];
    #pragma unroll
    for (int nt = 0; nt < 8; nt++)
        #pragma unroll
        for (int k = 0; k < 4; k++) O[nt][k] = 0.f;
    float m0 = -INFINITY, m1 = -INFINITY, l0 = 0.f, l1 = 0.f;

    const int r0 = w * 16 + (l >> 2), r1 = r0 + 8;
    const int gq0 = q0 + r0, gq1 = q0 + r1;
    const uint32_t nRow = (uint32_t)((l & 7) + ((l >> 4) & 1) * 8);
    const uint32_t kColB = (uint32_t)(((l >> 3) & 1) * 16);
    const uint32_t vRowP = (uint32_t)((l & 7) + ((l >> 3) & 1) * 8);
    const uint32_t vColB = (uint32_t)(((l >> 4) & 1) * 16);
    const uint32_t qbase = s0 + QOFF +
        (uint32_t)(w * 16 + (l & 7) + ((l >> 3) & 1) * 8) * FROWB + ((l >> 4) * 16);
    const __nv_bfloat16* bias0 = ebias + ((size_t)b * NT + gq0) * NT + 2 * (l & 3);
    const __nv_bfloat16* bias1 = ebias + ((size_t)b * NT + gq1) * NT + 2 * (l & 3);

    for (int jt = 0; jt < ntiles; jt++) {
        const int bsel = jt & 1;
        CP_WAIT0();
        __syncthreads();
        if (jt + 1 < ntiles) issue_kv(jt + 1, bsel ^ 1);

        // prefetch bias for this tile (hidden under QK MMAs)
        uint32_t breg[16];
        #pragma unroll
        for (int nt = 0; nt < 8; nt++) {
            breg[nt]     = *reinterpret_cast<const uint32_t*>(bias0 + jt * 64 + nt * 8);
            breg[8 + nt] = *reinterpret_cast<const uint32_t*>(bias1 + jt * 64 + nt * 8);
        }

        // ---- S = Q K^T (bf16x3) over 64 keys — already in log2 domain
        float acc[8][4];
        #pragma unroll
        for (int nt = 0; nt < 8; nt++)
            #pragma unroll
            for (int k = 0; k < 4; k++) acc[nt][k] = 0.f;

        const uint32_t kb = s0 + bsel * KVBUF64;
        #pragma unroll
        for (int ks = 0; ks < 4; ks++) {
            uint32_t qhf[4], qlf[4];
            ldsm4(qhf, qbase + ks * 32);
            ldsm4(qlf, qbase + QARR + ks * 32);
            #pragma unroll
            for (int np = 0; np < 4; np++) {
                uint32_t khf[4], klf[4];
                const uint32_t a = kb + (np * 16 + nRow) * FROWB + kColB + ks * 32;
                ldsm4(khf, a);
                ldsm4(klf, a + KVARR64);
                #pragma unroll
                for (int sub = 0; sub < 2; sub++) {
                    const int nt = np * 2 + sub;
                    mma_bf16(acc[nt], qhf, &khf[sub * 2]);
                    mma_bf16(acc[nt], qhf, &klf[sub * 2]);
                    mma_bf16(acc[nt], qlf, &khf[sub * 2]);
                }
            }
        }

        // ---- bias add (log2 domain) + causal mask + online softmax (exp2)
        float mx0 = -INFINITY, mx1 = -INFINITY;
        const bool masktile = (jt >= 2 * qb);
        #pragma unroll
        for (int nt = 0; nt < 8; nt++) {
            float2 bv0 = __bfloat1622float2(*reinterpret_cast<__nv_bfloat162*>(&breg[nt]));
            float2 bv1 = __bfloat1622float2(*reinterpret_cast<__nv_bfloat162*>(&breg[8 + nt]));
            float v0 = acc[nt][0] + bv0.x;
            float v1 = acc[nt][1] + bv0.y;
            float v2 = acc[nt][2] + bv1.x;
            float v3 = acc[nt][3] + bv1.y;
            if (masktile) {
                const int kc = jt * 64 + nt * 8 + 2 * (l & 3);
                if (kc > gq0)     v0 = -1e30f;
                if (kc + 1 > gq0) v1 = -1e30f;
                if (kc > gq1)     v2 = -1e30f;
                if (kc + 1 > gq1) v3 = -1e30f;
            }
            acc[nt][0] = v0; acc[nt][1] = v1; acc[nt][2] = v2; acc[nt][3] = v3;
            mx0 = fmaxf(mx0, fmaxf(v0, v1));
            mx1 = fmaxf(mx1, fmaxf(v2, v3));
        }
        mx0 = fmaxf(mx0, __shfl_xor_sync(0xffffffff, mx0, 1));
        mx0 = fmaxf(mx0, __shfl_xor_sync(0xffffffff, mx0, 2));
        mx1 = fmaxf(mx1, __shfl_xor_sync(0xffffffff, mx1, 1));
        mx1 = fmaxf(mx1, __shfl_xor_sync(0xffffffff, mx1, 2));

        const float mn0 = fmaxf(m0, mx0), mn1 = fmaxf(m1, mx1);
        const float c0 = fexp2(m0 - mn0), c1 = fexp2(m1 - mn1);
        float rs0 = 0.f, rs1 = 0.f;
        #pragma unroll
        for (int nt = 0; nt < 8; nt++) {
            const float p0 = fexp2(acc[nt][0] - mn0);
            const float p1 = fexp2(acc[nt][1] - mn0);
            const float p2 = fexp2(acc[nt][2] - mn1);
            const float p3 = fexp2(acc[nt][3] - mn1);
            acc[nt][0] = p0; acc[nt][1] = p1; acc[nt][2] = p2; acc[nt][3] = p3;
            rs0 += p0 + p1;
            rs1 += p2 + p3;
        }
        rs0 += __shfl_xor_sync(0xffffffff, rs0, 1);
        rs0 += __shfl_xor_sync(0xffffffff, rs0, 2);
        rs1 += __shfl_xor_sync(0xffffffff, rs1, 1);
        rs1 += __shfl_xor_sync(0xffffffff, rs1, 2);
        l0 = l0 * c0 + rs0;
        l1 = l1 * c1 + rs1;
        m0 = mn0; m1 = mn1;
        #pragma unroll
        for (int nt = 0; nt < 8; nt++) {
            O[nt][0] *= c0; O[nt][1] *= c0; O[nt][2] *= c1; O[nt][3] *= c1;
        }

        // ---- O += P V (bf16x3) over 64 keys
        const uint32_t vb = kb + 2 * KVARR64;
        #pragma unroll
        for (int kk = 0; kk < 4; kk++) {
            uint32_t phi[4], plo[4];
            phi[0] = packbf(acc[2 * kk][0], acc[2 * kk][1]);
            plo[0] = packlo(acc[2 * kk][0], acc[2 * kk][1], phi[0]);
            phi[1] = packbf(acc[2 * kk][2], acc[2 * kk][3]);
            plo[1] = packlo(acc[2 * kk][2], acc[2 * kk][3], phi[1]);
            phi[2] = packbf(acc[2 * kk + 1][0], acc[2 * kk + 1][1]);
            plo[2] = packlo(acc[2 * kk + 1][0], acc[2 * kk + 1][1], phi[2]);
            phi[3] = packbf(acc[2 * kk + 1][2], acc[2 * kk + 1][3]);
            plo[3] = packlo(acc[2 * kk + 1][2], acc[2 * kk + 1][3], phi[3]);
            #pragma unroll
            for (int nn = 0; nn < 4; nn++) {
                uint32_t vhf[4], vlf[4];
                const uint32_t va = vb + (kk * 16 + vRowP) * FROWB + nn * 32 + vColB;
                ldsm4t(vhf, va);
                ldsm4t(vlf, va + KVARR64);
                #pragma unroll
                for (int sub = 0; sub < 2; sub++) {
                    const int nt = nn * 2 + sub;
                    mma_bf16(O[nt], phi, &vhf[sub * 2]);
                    mma_bf16(O[nt], phi, &vlf[sub * 2]);
                    mma_bf16(O[nt], plo, &vhf[sub * 2]);
                }
            }
        }
    }

    // ---- epilogue: O/l -> bf16 hi/lo, [B,T,D] layout
    const float inv0 = 1.f / l0, inv1 = 1.f / l1;
    const size_t a0 = ((size_t)b * NT + gq0) * ND + h * NHD + 2 * (l & 3);
    const size_t a1 = ((size_t)b * NT + gq1) * ND + h * NHD + 2 * (l & 3);
    #pragma unroll
    for (int nt = 0; nt < 8; nt++) {
        const float o0 = O[nt][0] * inv0, o1 = O[nt][1] * inv0;
        const float o2 = O[nt][2] * inv1, o3 = O[nt][3] * inv1;
        const uint32_t h0 = packbf(o0, o1), lo0 = packlo(o0, o1, h0);
        const uint32_t h1 = packbf(o2, o3), lo1 = packlo(o2, o3, h1);
        *reinterpret_cast<uint32_t*>(out_hi + a0 + nt * 8) = h0;
        *reinterpret_cast<uint32_t*>(out_lo + a0 + nt * 8) = lo0;
        *reinterpret_cast<uint32_t*>(out_hi + a1 + nt * 8) = h1;
        *reinterpret_cast<uint32_t*>(out_lo + a1 + nt * 8) = lo1;
    }
}

// ---------------------------------------------------------------------------
extern "C" void kernel_launch(void* const* d_in, const int* in_sizes, int n_in,
                              void* d_out, int out_size)
{
    const float* x     = (const float*)d_in[0];
    const float* eb    = (const float*)d_in[1];
    const float* Wqkv  = (const float*)d_in[2];
    const float* bqkv  = (const float*)d_in[3];
    const float* Wout  = (const float*)d_in[4];
    const float* bout  = (const float*)d_in[5];
    float* out = (float*)d_out;

    __nv_bfloat16 *xhi, *xlo, *wqhi, *wqlo, *wohi, *wolo, *athi, *atlo;
    __nv_bfloat16 *qhi, *qlo, *khi2, *klo2, *vhi2, *vlo2, *ebbf;
    cudaGetSymbolAddress((void**)&xhi,  g_x_hi);
    cudaGetSymbolAddress((void**)&xlo,  g_x_lo);
    cudaGetSymbolAddress((void**)&wqhi, g_wq_hi);
    cudaGetSymbolAddress((void**)&wqlo, g_wq_lo);
    cudaGetSymbolAddress((void**)&wohi, g_wo_hi);
    cudaGetSymbolAddress((void**)&wolo, g_wo_lo);
    cudaGetSymbolAddress((void**)&athi, g_att_hi);
    cudaGetSymbolAddress((void**)&atlo, g_att_lo);
    cudaGetSymbolAddress((void**)&qhi,  g_q_hi);
    cudaGetSymbolAddress((void**)&qlo,  g_q_lo);
    cudaGetSymbolAddress((void**)&khi2, g_k_hi);
    cudaGetSymbolAddress((void**)&klo2, g_k_lo);
    cudaGetSymbolAddress((void**)&vhi2, g_v_hi);
    cudaGetSymbolAddress((void**)&vlo2, g_v_lo);
    cudaGetSymbolAddress((void**)&ebbf, g_eb_bf);

    const int M = NB * NT;   // 8192

    // [0] fused prepass (x split + both weight transpose-splits)
    prepass_kernel<<<BLK_SPLIT + BLK_TQKV + BLK_TWO, 256>>>(
        x, Wqkv, Wout, xhi, xlo, wqhi, wqlo, wohi, wolo);

    // [1] bias -> bf16 (pre-scaled by log2e)
    bias_to_bf16_kernel<<<(int)(((size_t)NB * NT * NT) / 4 / 256), 256>>>(eb, ebbf);

    const int gemm_smem = 2 * STG_BYTES;   // 81920 -> 2 CTAs/SM
    cudaFuncSetAttribute(gemm_bf16x3<0>, cudaFuncAttributeMaxDynamicSharedMemorySize, gemm_smem);
    cudaFuncSetAttribute(gemm_bf16x3<1>, cudaFuncAttributeMaxDynamicSharedMemorySize, gemm_smem);

    // [2] QKV projection, fused per-head split epilogue (q pre-scaled)
    gemm_bf16x3<1><<<dim3(3 * ND / 128, M / 128), 256, gemm_smem>>>(
        xhi, xlo, wqhi, wqlo, bqkv, nullptr,
        qhi, qlo, khi2, klo2, vhi2, vlo2, M, 3 * ND, ND);

    // [3] flash attention  <-- lands at ncu profile index 3
    cudaFuncSetAttribute(flash_mma, cudaFuncAttributeMaxDynamicSharedMemorySize, FLASH_SMEM);
    flash_mma<<<dim3(NT / 128, NH, NB), 256, FLASH_SMEM>>>(
        qhi, qlo, khi2, klo2, vhi2, vlo2, ebbf, athi, atlo);

    // [4] output projection (fp32 out + bias)
    gemm_bf16x3<0><<<dim3(ND / 128, M / 128), 256, gemm_smem>>>(
        athi, atlo, wohi, wolo, bout, out,
        nullptr, nullptr, nullptr, nullptr, nullptr, nullptr, M, ND, ND);
}

// round 11
// speedup vs baseline: 1.0085x; 1.0058x over previous
#include <cuda_runtime.h>
#include <cuda_bf16.h>
#include <math.h>
#include <stdint.h>

#define NB 4
#define NT 2048
#define ND 1024
#define NH 16
#define NHD 64

#define QSCALE 0.1803368801111244f   // 0.125 * log2(e)
#define LOG2E  1.4426950408889634f

// ---------------------------------------------------------------------------
// scratch (allocation-free rule: __device__ globals)
// ---------------------------------------------------------------------------
__device__ __align__(256) __nv_bfloat16 g_x_hi[(size_t)NB * NT * ND];
__device__ __align__(256) __nv_bfloat16 g_x_lo[(size_t)NB * NT * ND];
__device__ __align__(256) __nv_bfloat16 g_wq_hi[(size_t)3 * ND * ND];      // Wqkv^T [3D, D]
__device__ __align__(256) __nv_bfloat16 g_wq_lo[(size_t)3 * ND * ND];
__device__ __align__(256) __nv_bfloat16 g_wo_hi[(size_t)ND * ND];          // Wout^T [D, D]
__device__ __align__(256) __nv_bfloat16 g_wo_lo[(size_t)ND * ND];
__device__ __align__(256) __nv_bfloat16 g_att_hi[(size_t)NB * NT * ND];
__device__ __align__(256) __nv_bfloat16 g_att_lo[(size_t)NB * NT * ND];
// per-head split q/k/v: [B,H,T,64] bf16 (written by QKV GEMM epilogue; q pre-scaled)
__device__ __align__(256) __nv_bfloat16 g_q_hi[(size_t)NB * NH * NT * NHD];
__device__ __align__(256) __nv_bfloat16 g_q_lo[(size_t)NB * NH * NT * NHD];
__device__ __align__(256) __nv_bfloat16 g_k_hi[(size_t)NB * NH * NT * NHD];
__device__ __align__(256) __nv_bfloat16 g_k_lo[(size_t)NB * NH * NT * NHD];
__device__ __align__(256) __nv_bfloat16 g_v_hi[(size_t)NB * NH * NT * NHD];
__device__ __align__(256) __nv_bfloat16 g_v_lo[(size_t)NB * NH * NT * NHD];
// entity bias in bf16, pre-multiplied by log2(e)
__device__ __align__(256) __nv_bfloat16 g_eb_bf[(size_t)NB * NT * NT];

// ---------------------------------------------------------------------------
// PTX helpers (all baseline sm_80+)
// ---------------------------------------------------------------------------
__device__ __forceinline__ uint32_t smem_u32(const void* p) {
    uint32_t a;
    asm("{ .reg .u64 t; cvta.to.shared.u64 t, %1; cvt.u32.u64 %0, t; }" : "=r"(a) : "l"(p));
    return a;
}
__device__ __forceinline__ void ldsm4(uint32_t* r, uint32_t addr) {
    asm volatile("ldmatrix.sync.aligned.m8n8.x4.shared.b16 {%0,%1,%2,%3}, [%4];"
                 : "=r"(r[0]), "=r"(r[1]), "=r"(r[2]), "=r"(r[3]) : "r"(addr));
}
__device__ __forceinline__ void ldsm4t(uint32_t* r, uint32_t addr) {
    asm volatile("ldmatrix.sync.aligned.m8n8.x4.trans.shared.b16 {%0,%1,%2,%3}, [%4];"
                 : "=r"(r[0]), "=r"(r[1]), "=r"(r[2]), "=r"(r[3]) : "r"(addr));
}
__device__ __forceinline__ void mma_bf16(float* c, const uint32_t* a, const uint32_t* b) {
    asm volatile(
        "mma.sync.aligned.m16n8k16.row.col.f32.bf16.bf16.f32 "
        "{%0,%1,%2,%3}, {%4,%5,%6,%7}, {%8,%9}, {%0,%1,%2,%3};"
        : "+f"(c[0]), "+f"(c[1]), "+f"(c[2]), "+f"(c[3])
        : "r"(a[0]), "r"(a[1]), "r"(a[2]), "r"(a[3]), "r"(b[0]), "r"(b[1]));
}
__device__ __forceinline__ void cp16(uint32_t smem, const void* g) {
    asm volatile("cp.async.cg.shared.global [%0], [%1], 16;" :: "r"(smem), "l"(g));
}
#define CP_COMMIT() asm volatile("cp.async.commit_group;" ::: "memory")
#define CP_WAIT1()  asm volatile("cp.async.wait_group 1;" ::: "memory")
#define CP_WAIT0()  asm volatile("cp.async.wait_group 0;" ::: "memory")

__device__ __forceinline__ float fexp2(float x) {
    float r;
    asm("ex2.approx.f32 %0, %1;" : "=f"(r) : "f"(x));
    return r;
}
__device__ __forceinline__ uint32_t packbf(float a, float b) {
    __nv_bfloat162 t = __float22bfloat162_rn(make_float2(a, b));
    return *reinterpret_cast<uint32_t*>(&t);
}
__device__ __forceinline__ uint32_t packlo(float a, float b, uint32_t hi) {
    __nv_bfloat162 h = *reinterpret_cast<__nv_bfloat162*>(&hi);
    float2 hf = __bfloat1622float2(h);
    return packbf(a - hf.x, b - hf.y);
}

// ---------------------------------------------------------------------------
// fused prepass: x split + both weight transpose-splits (launch 0)
// ---------------------------------------------------------------------------
#define BLK_SPLIT 32768
#define BLK_TQKV  3072
#define BLK_TWO   1024

__global__ __launch_bounds__(256)
void prepass_kernel(const float* __restrict__ x,
                    const float* __restrict__ Wqkv,
                    const float* __restrict__ Wout,
                    __nv_bfloat16* __restrict__ xhi, __nv_bfloat16* __restrict__ xlo,
                    __nv_bfloat16* __restrict__ wqhi, __nv_bfloat16* __restrict__ wqlo,
                    __nv_bfloat16* __restrict__ wohi, __nv_bfloat16* __restrict__ wolo)
{
    __shared__ float t[32][33];
    const int bid = blockIdx.x;
    const int tid = threadIdx.x;

    if (bid < BLK_SPLIT) {
        const int i = bid * 256 + tid;
        float v = x[i];
        __nv_bfloat16 h = __float2bfloat16(v);
        xhi[i] = h;
        xlo[i] = __float2bfloat16(v - __bfloat162float(h));
        return;
    }

    const float* W;
    __nv_bfloat16 *Thi, *Tlo;
    int N, tb;
    if (bid < BLK_SPLIT + BLK_TQKV) {
        tb = bid - BLK_SPLIT; W = Wqkv; Thi = wqhi; Tlo = wqlo; N = 3 * ND;
    } else {
        tb = bid - BLK_SPLIT - BLK_TQKV; W = Wout; Thi = wohi; Tlo = wolo; N = ND;
    }
    const int K = ND;
    const int n0 = (tb % (N / 32)) * 32;
    const int k0 = (tb / (N / 32)) * 32;
    const int tx = tid & 31, ty = tid >> 5;
    #pragma unroll
    for (int j = 0; j < 32; j += 8)
        t[ty + j][tx] = W[(size_t)(k0 + ty + j) * N + n0 + tx];
    __syncthreads();
    #pragma unroll
    for (int j = 0; j < 32; j += 8) {
        float v = t[tx][ty + j];
        __nv_bfloat16 h = __float2bfloat16(v);
        size_t o = (size_t)(n0 + ty + j) * K + k0 + tx;
        Thi[o] = h;
        Tlo[o] = __float2bfloat16(v - __bfloat162float(h));
    }
}

// ---------------------------------------------------------------------------
// entity bias fp32 -> bf16 * log2(e)   (launch 1)
// ---------------------------------------------------------------------------
__global__ __launch_bounds__(256)
void bias_to_bf16_kernel(const float* __restrict__ src, __nv_bfloat16* __restrict__ dst)
{
    const size_t i = ((size_t)blockIdx.x * 256 + threadIdx.x) * 4;
    const float4 v = *reinterpret_cast<const float4*>(src + i);
    uint32_t p0 = packbf(v.x * LOG2E, v.y * LOG2E);
    uint32_t p1 = packbf(v.z * LOG2E, v.w * LOG2E);
    *reinterpret_cast<uint32_t*>(dst + i)     = p0;
    *reinterpret_cast<uint32_t*>(dst + i + 2) = p1;
}

// ---------------------------------------------------------------------------
// mma.sync bf16x3 GEMM (proven): 2-stage pipeline, 2 CTAs/SM.
// ---------------------------------------------------------------------------
#define STG_BYTES 40960
#define T_AHI 0
#define T_ALO 10240
#define T_BHI 20480
#define T_BLO 30720

template <int MODE>
__global__ __launch_bounds__(256, 2)
void gemm_bf16x3(const __nv_bfloat16* __restrict__ Ahi, const __nv_bfloat16* __restrict__ Alo,
                 const __nv_bfloat16* __restrict__ Bhi, const __nv_bfloat16* __restrict__ Blo,
                 const float* __restrict__ bias, float* __restrict__ C,
                 __nv_bfloat16* __restrict__ qhi, __nv_bfloat16* __restrict__ qlo,
                 __nv_bfloat16* __restrict__ khi, __nv_bfloat16* __restrict__ klo,
                 __nv_bfloat16* __restrict__ vhi, __nv_bfloat16* __restrict__ vlo,
                 int M, int N, int K)
{
    extern __shared__ char dynsm[];
    const uint32_t sb0 = smem_u32(dynsm);

    const int tid = threadIdx.x;
    const int wid = tid >> 5;
    const int l   = tid & 31;
    const int wm  = wid >> 1;
    const int wn  = wid & 1;
    const size_t m0 = (size_t)blockIdx.y * 128;
    const size_t n0 = (size_t)blockIdx.x * 128;

    const int r1 = tid >> 2;
    const int r2 = r1 + 64;
    const int cc = (tid & 3);
    const uint32_t sm_off1 = (uint32_t)r1 * 80 + cc * 16;
    const uint32_t sm_off2 = (uint32_t)r2 * 80 + cc * 16;

    const int nchunks = K >> 5;

    auto issue_stage = [&](int c, int buf) {
        const int kc = c << 5;
        const uint32_t sb = sb0 + buf * STG_BYTES;
        cp16(sb + T_AHI + sm_off1, Ahi + (m0 + r1) * K + kc + cc * 8);
        cp16(sb + T_AHI + sm_off2, Ahi + (m0 + r2) * K + kc + cc * 8);
        cp16(sb + T_ALO + sm_off1, Alo + (m0 + r1) * K + kc + cc * 8);
        cp16(sb + T_ALO + sm_off2, Alo + (m0 + r2) * K + kc + cc * 8);
        cp16(sb + T_BHI + sm_off1, Bhi + (n0 + r1) * K + kc + cc * 8);
        cp16(sb + T_BHI + sm_off2, Bhi + (n0 + r2) * K + kc + cc * 8);
        cp16(sb + T_BLO + sm_off1, Blo + (n0 + r1) * K + kc + cc * 8);
        cp16(sb + T_BLO + sm_off2, Blo + (n0 + r2) * K + kc + cc * 8);
        CP_COMMIT();
    };

    const int aRow = (l & 7) + ((l >> 3) & 1) * 8;
    const int aCol8 = (l >> 4) * 8;
    const int bRow = (l & 7) + ((l >> 4) & 1) * 8;
    const int bCol8 = ((l >> 3) & 1) * 8;

    float acc[2][8][4];
    #pragma unroll
    for (int mt = 0; mt < 2; mt++)
        #pragma unroll
        for (int nt = 0; nt < 8; nt++)
            #pragma unroll
            for (int k = 0; k < 4; k++) acc[mt][nt][k] = 0.f;

    issue_stage(0, 0);

    for (int c = 0; c < nchunks; c++) {
        if (c + 1 < nchunks) {
            issue_stage(c + 1, (c + 1) & 1);
            CP_WAIT1();
        } else {
            CP_WAIT0();
        }
        __syncthreads();

        const uint32_t sb = sb0 + (c & 1) * STG_BYTES;
        const uint32_t aBase = sb + (uint32_t)(wm * 32 + aRow) * 80 + aCol8 * 2;
        const uint32_t bBase = sb + (uint32_t)(wn * 64 + bRow) * 80 + bCol8 * 2;

        #pragma unroll
        for (int ks = 0; ks < 2; ks++) {
            uint32_t ah[2][4], al4[2][4];
            #pragma unroll
            for (int mt = 0; mt < 2; mt++) {
                ldsm4(ah[mt],  aBase + T_AHI + mt * (16 * 80) + ks * 32);
                ldsm4(al4[mt], aBase + T_ALO + mt * (16 * 80) + ks * 32);
            }
            #pragma unroll
            for (int np = 0; np < 4; np++) {
                uint32_t bh[4], bl4[4];
                ldsm4(bh,  bBase + T_BHI + np * (16 * 80) + ks * 32);
                ldsm4(bl4, bBase + T_BLO + np * (16 * 80) + ks * 32);
                #pragma unroll
                for (int mt = 0; mt < 2; mt++)
                    #pragma unroll
                    for (int sub = 0; sub < 2; sub++) {
                        const int nt = np * 2 + sub;
                        mma_bf16(acc[mt][nt], ah[mt],  &bh[sub * 2]);
                        mma_bf16(acc[mt][nt], ah[mt],  &bl4[sub * 2]);
                        mma_bf16(acc[mt][nt], al4[mt], &bh[sub * 2]);
                    }
            }
        }
        __syncthreads();
    }

    if (MODE == 0) {
        #pragma unroll
        for (int mt = 0; mt < 2; mt++) {
            const size_t row0 = m0 + wm * 32 + mt * 16 + (l >> 2);
            #pragma unroll
            for (int nt = 0; nt < 8; nt++) {
                const size_t col = n0 + wn * 64 + nt * 8 + (l & 3) * 2;
                const float b0 = bias[col], b1 = bias[col + 1];
                float2 v0 = { acc[mt][nt][0] + b0, acc[mt][nt][1] + b1 };
                float2 v1 = { acc[mt][nt][2] + b0, acc[mt][nt][3] + b1 };
                *reinterpret_cast<float2*>(&C[row0 * N + col]) = v0;
                *reinterpret_cast<float2*>(&C[(row0 + 8) * N + col]) = v1;
            }
        }
    } else {
        const int colbase = (int)n0 + wn * 64;
        const int sel = colbase >> 10;
        const int head = (colbase >> 6) & 15;
        const float qs = (sel == 0) ? QSCALE : 1.0f;
        __nv_bfloat16* dh = (sel == 0) ? qhi : (sel == 1) ? khi : vhi;
        __nv_bfloat16* dl = (sel == 0) ? qlo : (sel == 1) ? klo : vlo;
        #pragma unroll
        for (int mt = 0; mt < 2; mt++) {
            const int row0 = (int)m0 + wm * 32 + mt * 16 + (l >> 2);
            const int bb = row0 >> 11;
            const int t0 = row0 & 2047;
            const size_t base = ((size_t)(bb * NH + head) * NT + t0) * NHD;
            #pragma unroll
            for (int nt = 0; nt < 8; nt++) {
                const int col = colbase + nt * 8 + (l & 3) * 2;
                const int d = col & 63;
                const float b0 = bias[col], b1 = bias[col + 1];
                const float v0 = (acc[mt][nt][0] + b0) * qs, v1 = (acc[mt][nt][1] + b1) * qs;
                const float v2 = (acc[mt][nt][2] + b0) * qs, v3 = (acc[mt][nt][3] + b1) * qs;
                const uint32_t h0 = packbf(v0, v1), lo0 = packlo(v0, v1, h0);
                const uint32_t h1 = packbf(v2, v3), lo1 = packlo(v2, v3, h1);
                *reinterpret_cast<uint32_t*>(dh + base + d)            = h0;
                *reinterpret_cast<uint32_t*>(dl + base + d)            = lo0;
                *reinterpret_cast<uint32_t*>(dh + base + 8 * NHD + d)  = h1;
                *reinterpret_cast<uint32_t*>(dl + base + 8 * NHD + d)  = lo1;
            }
        }
    }
}

// ---------------------------------------------------------------------------
// Tensor-core flash attention v2 — LDSM-bound fix:
// 128 threads, 4 warps, warp M-tile = 32 q rows (two m16 tiles) => K/V
// fragments reused 2x => smem traffic/FLOP halved. 2 CTAs/SM (regs free: 256).
// Per-warp causal tile skipping. log2-domain softmax (ex2).
// smem: 2 x 36864 KV + 36864 Q = 110592 B.
// ---------------------------------------------------------------------------
#define FROWB 144
#define KVARR64 (64 * FROWB)          // 9216
#define KVBUF64 (4 * KVARR64)         // 36864 : Khi|Klo|Vhi|Vlo
#define QOFF (2 * KVBUF64)            // 73728
#define QARR (128 * FROWB)            // 18432
#define FLASH_SMEM (QOFF + 2 * QARR)  // 110592

__global__ __launch_bounds__(128, 2)
void flash_mma(const __nv_bfloat16* __restrict__ qhi, const __nv_bfloat16* __restrict__ qlo,
               const __nv_bfloat16* __restrict__ khi, const __nv_bfloat16* __restrict__ klo,
               const __nv_bfloat16* __restrict__ vhi, const __nv_bfloat16* __restrict__ vlo,
               const __nv_bfloat16* __restrict__ ebias,
               __nv_bfloat16* __restrict__ out_hi, __nv_bfloat16* __restrict__ out_lo)
{
    extern __shared__ char sm[];
    const uint32_t s0 = smem_u32(sm);
    const int tid = threadIdx.x, w = tid >> 5, l = tid & 31;
    const int qb = 15 - blockIdx.x;          // heavy CTAs first
    const int h = blockIdx.y, b = blockIdx.z;
    const int q0 = qb * 128;
    const size_t hoff = (size_t)(b * NH + h) * NT * NHD;
    const int ntiles = 2 * qb + 2;           // key tiles of 64

    auto issue_kv = [&](int jt2, int bsel2) {
        #pragma unroll
        for (int i = 0; i < 16; i++) {
            const int ck = tid + i * 128;            // 0..2047
            const int arr = ck >> 9;                 // 0..3
            const int row = (ck >> 3) & 63;
            const int seg = ck & 7;
            const size_t go = hoff + (size_t)(jt2 * 64 + row) * NHD + seg * 8;
            const __nv_bfloat16* src = (arr == 0) ? khi + go : (arr == 1) ? klo + go
                                      : (arr == 2) ? vhi + go : vlo + go;
            cp16(s0 + bsel2 * KVBUF64 + arr * KVARR64 + row * FROWB + seg * 16, src);
        }
        CP_COMMIT();
    };

    // prologue: Q (128 rows hi+lo) -> persistent region, KV(0) -> buf0
    #pragma unroll
    for (int i = 0; i < 16; i++) {
        const int cq = tid + i * 128;                // 0..2047
        const int arr = cq >> 10;                    // 0=hi,1=lo
        const int row = (cq >> 3) & 127;
        const int seg = cq & 7;
        const __nv_bfloat16* src = (arr ? qlo : qhi) + hoff + (size_t)(q0 + row) * NHD + seg * 8;
        cp16(s0 + QOFF + arr * QARR + row * FROWB + seg * 16, src);
    }
    CP_COMMIT();
    issue_kv(0, 0);

    float O[2][8][4];
    #pragma unroll
    for (int mt = 0; mt < 2; mt++)
        #pragma unroll
        for (int nt = 0; nt < 8; nt++)
            #pragma unroll
            for (int k = 0; k < 4; k++) O[mt][nt][k] = 0.f;
    float ms[4] = {-INFINITY, -INFINITY, -INFINITY, -INFINITY};
    float ls[4] = {0.f, 0.f, 0.f, 0.f};

    // rows: mt in {0,1}, half in {0,1}: gq[mt*2+half] = q0 + w*32 + mt*16 + half*8 + (l>>2)
    int gq[4];
    #pragma unroll
    for (int i = 0; i < 4; i++) gq[i] = q0 + w * 32 + (i >> 1) * 16 + (i & 1) * 8 + (l >> 2);
    const int gq_max_warp = q0 + w * 32 + 31;
    const int warp_row0   = q0 + w * 32;

    const uint32_t nRow  = (uint32_t)((l & 7) + ((l >> 4) & 1) * 8);
    const uint32_t kColB = (uint32_t)(((l >> 3) & 1) * 16);
    const uint32_t vRowP = (uint32_t)((l & 7) + ((l >> 3) & 1) * 8);
    const uint32_t vColB = (uint32_t)(((l >> 4) & 1) * 16);
    const uint32_t qb0 = s0 + QOFF +
        (uint32_t)(w * 32 + (l & 7) + ((l >> 3) & 1) * 8) * FROWB + ((l >> 4) * 16);

    const __nv_bfloat16* biasp[4];
    #pragma unroll
    for (int i = 0; i < 4; i++)
        biasp[i] = ebias + ((size_t)b * NT + gq[i]) * NT + 2 * (l & 3);

    for (int jt = 0; jt < ntiles; jt++) {
        const int bsel = jt & 1;
        CP_WAIT0();
        __syncthreads();
        if (jt + 1 < ntiles) issue_kv(jt + 1, bsel ^ 1);

        if (jt * 64 > gq_max_warp) continue;   // tile fully above this warp's rows

        // ---- S = Q K^T (bf16x3), two m16 tiles share each K fragment
        float acc[2][8][4];
        #pragma unroll
        for (int mt = 0; mt < 2; mt++)
            #pragma unroll
            for (int nt = 0; nt < 8; nt++)
                #pragma unroll
                for (int k = 0; k < 4; k++) acc[mt][nt][k] = 0.f;

        const uint32_t kb = s0 + bsel * KVBUF64;
        #pragma unroll
        for (int ks = 0; ks < 4; ks++) {
            uint32_t qh0[4], ql0[4], qh1[4], ql1[4];
            const uint32_t qa = qb0 + ks * 32;
            ldsm4(qh0, qa);
            ldsm4(ql0, qa + QARR);
            ldsm4(qh1, qa + 16 * FROWB);
            ldsm4(ql1, qa + 16 * FROWB + QARR);
            #pragma unroll
            for (int np = 0; np < 4; np++) {
                uint32_t khf[4], klf[4];
                const uint32_t a = kb + (np * 16 + nRow) * FROWB + kColB + ks * 32;
                ldsm4(khf, a);
                ldsm4(klf, a + KVARR64);
                #pragma unroll
                for (int sub = 0; sub < 2; sub++) {
                    const int nt = np * 2 + sub;
                    mma_bf16(acc[0][nt], qh0, &khf[sub * 2]);
                    mma_bf16(acc[0][nt], qh0, &klf[sub * 2]);
                    mma_bf16(acc[0][nt], ql0, &khf[sub * 2]);
                    mma_bf16(acc[1][nt], qh1, &khf[sub * 2]);
                    mma_bf16(acc[1][nt], qh1, &klf[sub * 2]);
                    mma_bf16(acc[1][nt], ql1, &khf[sub * 2]);
                }
            }
        }

        // ---- softmax per m-tile (log2 domain)
        const bool maskw = (jt * 64 + 63 > warp_row0);
        #pragma unroll
        for (int mt = 0; mt < 2; mt++) {
            uint32_t breg[16];
            #pragma unroll
            for (int nt = 0; nt < 8; nt++) {
                breg[nt]     = *reinterpret_cast<const uint32_t*>(biasp[mt * 2]     + jt * 64 + nt * 8);
                breg[8 + nt] = *reinterpret_cast<const uint32_t*>(biasp[mt * 2 + 1] + jt * 64 + nt * 8);
            }
            float mx0 = -INFINITY, mx1 = -INFINITY;
            #pragma unroll
            for (int nt = 0; nt < 8; nt++) {
                float2 bv0 = __bfloat1622float2(*reinterpret_cast<__nv_bfloat162*>(&breg[nt]));
                float2 bv1 = __bfloat1622float2(*reinterpret_cast<__nv_bfloat162*>(&breg[8 + nt]));
                float v0 = acc[mt][nt][0] + bv0.x;
                float v1 = acc[mt][nt][1] + bv0.y;
                float v2 = acc[mt][nt][2] + bv1.x;
                float v3 = acc[mt][nt][3] + bv1.y;
                if (maskw) {
                    const int kc = jt * 64 + nt * 8 + 2 * (l & 3);
                    if (kc > gq[mt * 2])         v0 = -1e30f;
                    if (kc + 1 > gq[mt * 2])     v1 = -1e30f;
                    if (kc > gq[mt * 2 + 1])     v2 = -1e30f;
                    if (kc + 1 > gq[mt * 2 + 1]) v3 = -1e30f;
                }
                acc[mt][nt][0] = v0; acc[mt][nt][1] = v1;
                acc[mt][nt][2] = v2; acc[mt][nt][3] = v3;
                mx0 = fmaxf(mx0, fmaxf(v0, v1));
                mx1 = fmaxf(mx1, fmaxf(v2, v3));
            }
            mx0 = fmaxf(mx0, __shfl_xor_sync(0xffffffff, mx0, 1));
            mx0 = fmaxf(mx0, __shfl_xor_sync(0xffffffff, mx0, 2));
            mx1 = fmaxf(mx1, __shfl_xor_sync(0xffffffff, mx1, 1));
            mx1 = fmaxf(mx1, __shfl_xor_sync(0xffffffff, mx1, 2));

            const float mn0 = fmaxf(ms[mt * 2], mx0), mn1 = fmaxf(ms[mt * 2 + 1], mx1);
            const float c0 = fexp2(ms[mt * 2] - mn0), c1 = fexp2(ms[mt * 2 + 1] - mn1);
            float rs0 = 0.f, rs1 = 0.f;
            #pragma unroll
            for (int nt = 0; nt < 8; nt++) {
                const float p0 = fexp2(acc[mt][nt][0] - mn0);
                const float p1 = fexp2(acc[mt][nt][1] - mn0);
                const float p2 = fexp2(acc[mt][nt][2] - mn1);
                const float p3 = fexp2(acc[mt][nt][3] - mn1);
                acc[mt][nt][0] = p0; acc[mt][nt][1] = p1;
                acc[mt][nt][2] = p2; acc[mt][nt][3] = p3;
                rs0 += p0 + p1;
                rs1 += p2 + p3;
            }
            rs0 += __shfl_xor_sync(0xffffffff, rs0, 1);
            rs0 += __shfl_xor_sync(0xffffffff, rs0, 2);
            rs1 += __shfl_xor_sync(0xffffffff, rs1, 1);
            rs1 += __shfl_xor_sync(0xffffffff, rs1, 2);
            ls[mt * 2]     = ls[mt * 2] * c0 + rs0;
            ls[mt * 2 + 1] = ls[mt * 2 + 1] * c1 + rs1;
            ms[mt * 2]     = mn0;
            ms[mt * 2 + 1] = mn1;
            #pragma unroll
            for (int nt = 0; nt < 8; nt++) {
                O[mt][nt][0] *= c0; O[mt][nt][1] *= c0;
                O[mt][nt][2] *= c1; O[mt][nt][3] *= c1;
            }
        }

        // ---- O += P V (bf16x3), V fragments shared across both m-tiles
        const uint32_t vb = kb + 2 * KVARR64;
        #pragma unroll
        for (int kk = 0; kk < 4; kk++) {
            uint32_t phi0[4], plo0[4], phi1[4], plo1[4];
            phi0[0] = packbf(acc[0][2 * kk][0], acc[0][2 * kk][1]);
            plo0[0] = packlo(acc[0][2 * kk][0], acc[0][2 * kk][1], phi0[0]);
            phi0[1] = packbf(acc[0][2 * kk][2], acc[0][2 * kk][3]);
            plo0[1] = packlo(acc[0][2 * kk][2], acc[0][2 * kk][3], phi0[1]);
            phi0[2] = packbf(acc[0][2 * kk + 1][0], acc[0][2 * kk + 1][1]);
            plo0[2] = packlo(acc[0][2 * kk + 1][0], acc[0][2 * kk + 1][1], phi0[2]);
            phi0[3] = packbf(acc[0][2 * kk + 1][2], acc[0][2 * kk + 1][3]);
            plo0[3] = packlo(acc[0][2 * kk + 1][2], acc[0][2 * kk + 1][3], phi0[3]);
            phi1[0] = packbf(acc[1][2 * kk][0], acc[1][2 * kk][1]);
            plo1[0] = packlo(acc[1][2 * kk][0], acc[1][2 * kk][1], phi1[0]);
            phi1[1] = packbf(acc[1][2 * kk][2], acc[1][2 * kk][3]);
            plo1[1] = packlo(acc[1][2 * kk][2], acc[1][2 * kk][3], phi1[1]);
            phi1[2] = packbf(acc[1][2 * kk + 1][0], acc[1][2 * kk + 1][1]);
            plo1[2] = packlo(acc[1][2 * kk + 1][0], acc[1][2 * kk + 1][1], phi1[2]);
            phi1[3] = packbf(acc[1][2 * kk + 1][2], acc[1][2 * kk + 1][3]);
            plo1[3] = packlo(acc[1][2 * kk + 1][2], acc[1][2 * kk + 1][3], phi1[3]);
            #pragma unroll
            for (int nn = 0; nn < 4; nn++) {
                uint32_t vhf[4], vlf[4];
                const uint32_t va = vb + (kk * 16 + vRowP) * FROWB + nn * 32 + vColB;
                ldsm4t(vhf, va);
                ldsm4t(vlf, va + KVARR64);
                #pragma unroll
                for (int sub = 0; sub < 2; sub++) {
                    const int nt = nn * 2 + sub;
                    mma_bf16(O[0][nt], phi0, &vhf[sub * 2]);
                    mma_bf16(O[0][nt], phi0, &vlf[sub * 2]);
                    mma_bf16(O[0][nt], plo0, &vhf[sub * 2]);
                    mma_bf16(O[1][nt], phi1, &vhf[sub * 2]);
                    mma_bf16(O[1][nt], phi1, &vlf[sub * 2]);
                    mma_bf16(O[1][nt], plo1, &vhf[sub * 2]);
                }
            }
        }
    }

    // ---- epilogue: O/l -> bf16 hi/lo, [B,T,D] layout
    #pragma unroll
    for (int mt = 0; mt < 2; mt++) {
        const float inv0 = 1.f / ls[mt * 2], inv1 = 1.f / ls[mt * 2 + 1];
        const size_t a0 = ((size_t)b * NT + gq[mt * 2])     * ND + h * NHD + 2 * (l & 3);
        const size_t a1 = ((size_t)b * NT + gq[mt * 2 + 1]) * ND + h * NHD + 2 * (l & 3);
        #pragma unroll
        for (int nt = 0; nt < 8; nt++) {
            const float o0 = O[mt][nt][0] * inv0, o1 = O[mt][nt][1] * inv0;
            const float o2 = O[mt][nt][2] * inv1, o3 = O[mt][nt][3] * inv1;
            const uint32_t h0 = packbf(o0, o1), lo0 = packlo(o0, o1, h0);
            const uint32_t h1 = packbf(o2, o3), lo1 = packlo(o2, o3, h1);
            *reinterpret_cast<uint32_t*>(out_hi + a0 + nt * 8) = h0;
            *reinterpret_cast<uint32_t*>(out_lo + a0 + nt * 8) = lo0;
            *reinterpret_cast<uint32_t*>(out_hi + a1 + nt * 8) = h1;
            *reinterpret_cast<uint32_t*>(out_lo + a1 + nt * 8) = lo1;
        }
    }
}

// ---------------------------------------------------------------------------
extern "C" void kernel_launch(void* const* d_in, const int* in_sizes, int n_in,
                              void* d_out, int out_size)
{
    const float* x     = (const float*)d_in[0];
    const float* eb    = (const float*)d_in[1];
    const float* Wqkv  = (const float*)d_in[2];
    const float* bqkv  = (const float*)d_in[3];
    const float* Wout  = (const float*)d_in[4];
    const float* bout  = (const float*)d_in[5];
    float* out = (float*)d_out;

    __nv_bfloat16 *xhi, *xlo, *wqhi, *wqlo, *wohi, *wolo, *athi, *atlo;
    __nv_bfloat16 *qhi, *qlo, *khi2, *klo2, *vhi2, *vlo2, *ebbf;
    cudaGetSymbolAddress((void**)&xhi,  g_x_hi);
    cudaGetSymbolAddress((void**)&xlo,  g_x_lo);
    cudaGetSymbolAddress((void**)&wqhi, g_wq_hi);
    cudaGetSymbolAddress((void**)&wqlo, g_wq_lo);
    cudaGetSymbolAddress((void**)&wohi, g_wo_hi);
    cudaGetSymbolAddress((void**)&wolo, g_wo_lo);
    cudaGetSymbolAddress((void**)&athi, g_att_hi);
    cudaGetSymbolAddress((void**)&atlo, g_att_lo);
    cudaGetSymbolAddress((void**)&qhi,  g_q_hi);
    cudaGetSymbolAddress((void**)&qlo,  g_q_lo);
    cudaGetSymbolAddress((void**)&khi2, g_k_hi);
    cudaGetSymbolAddress((void**)&klo2, g_k_lo);
    cudaGetSymbolAddress((void**)&vhi2, g_v_hi);
    cudaGetSymbolAddress((void**)&vlo2, g_v_lo);
    cudaGetSymbolAddress((void**)&ebbf, g_eb_bf);

    const int M = NB * NT;   // 8192

    // [0] fused prepass
    prepass_kernel<<<BLK_SPLIT + BLK_TQKV + BLK_TWO, 256>>>(
        x, Wqkv, Wout, xhi, xlo, wqhi, wqlo, wohi, wolo);

    // [1] bias -> bf16 (pre-scaled by log2e)
    bias_to_bf16_kernel<<<(int)(((size_t)NB * NT * NT) / 4 / 256), 256>>>(eb, ebbf);

    const int gemm_smem = 2 * STG_BYTES;
    cudaFuncSetAttribute(gemm_bf16x3<0>, cudaFuncAttributeMaxDynamicSharedMemorySize, gemm_smem);
    cudaFuncSetAttribute(gemm_bf16x3<1>, cudaFuncAttributeMaxDynamicSharedMemorySize, gemm_smem);

    // [2] QKV projection, fused per-head split epilogue (q pre-scaled)
    gemm_bf16x3<1><<<dim3(3 * ND / 128, M / 128), 256, gemm_smem>>>(
        xhi, xlo, wqhi, wqlo, bqkv, nullptr,
        qhi, qlo, khi2, klo2, vhi2, vlo2, M, 3 * ND, ND);

    // [3] flash attention v2 (128 thr, warp M=32)  <-- ncu profile index 3
    cudaFuncSetAttribute(flash_mma, cudaFuncAttributeMaxDynamicSharedMemorySize, FLASH_SMEM);
    flash_mma<<<dim3(NT / 128, NH, NB), 128, FLASH_SMEM>>>(
        qhi, qlo, khi2, klo2, vhi2, vlo2, ebbf, athi, atlo);

    // [4] output projection
    gemm_bf16x3<0><<<dim3(ND / 128, M / 128), 256, gemm_smem>>>(
        athi, atlo, wohi, wolo, bout, out,
        nullptr, nullptr, nullptr, nullptr, nullptr, nullptr, M, ND, ND);
}

// round 12
// speedup vs baseline: 1.4110x; 1.3991x over previous
#include <cuda_runtime.h>
#include <cuda_fp16.h>
#include <cuda_bf16.h>
#include <math.h>
#include <stdint.h>

#define NB 4
#define NT 2048
#define ND 1024
#define NH 16
#define NHD 64

#define QSCALE 0.1803368801111244f   // 0.125 * log2(e)
#define LOG2E  1.4426950408889634f

// ---------------------------------------------------------------------------
// scratch (allocation-free rule: __device__ globals)
// fp16 split: A-side operands keep hi+lo; B-side operands are hi ONLY.
// ---------------------------------------------------------------------------
__device__ __align__(256) __half g_x_hi[(size_t)NB * NT * ND];
__device__ __align__(256) __half g_x_lo[(size_t)NB * NT * ND];
__device__ __align__(256) __half g_wq_hi[(size_t)3 * ND * ND];    // Wqkv^T [3D, D]
__device__ __align__(256) __half g_wo_hi[(size_t)ND * ND];        // Wout^T [D, D]
__device__ __align__(256) __half g_att_hi[(size_t)NB * NT * ND];
__device__ __align__(256) __half g_att_lo[(size_t)NB * NT * ND];
// per-head split q/k/v: [B,H,T,64] fp16 (q: hi+lo, k/v: hi only; q pre-scaled)
__device__ __align__(256) __half g_q_hi[(size_t)NB * NH * NT * NHD];
__device__ __align__(256) __half g_q_lo[(size_t)NB * NH * NT * NHD];
__device__ __align__(256) __half g_k_hi[(size_t)NB * NH * NT * NHD];
__device__ __align__(256) __half g_v_hi[(size_t)NB * NH * NT * NHD];
// entity bias in bf16, pre-multiplied by log2(e)
__device__ __align__(256) __nv_bfloat16 g_eb_bf[(size_t)NB * NT * NT];

// ---------------------------------------------------------------------------
// PTX helpers (all baseline sm_80+)
// ---------------------------------------------------------------------------
__device__ __forceinline__ uint32_t smem_u32(const void* p) {
    uint32_t a;
    asm("{ .reg .u64 t; cvta.to.shared.u64 t, %1; cvt.u32.u64 %0, t; }" : "=r"(a) : "l"(p));
    return a;
}
__device__ __forceinline__ void ldsm4(uint32_t* r, uint32_t addr) {
    asm volatile("ldmatrix.sync.aligned.m8n8.x4.shared.b16 {%0,%1,%2,%3}, [%4];"
                 : "=r"(r[0]), "=r"(r[1]), "=r"(r[2]), "=r"(r[3]) : "r"(addr));
}
__device__ __forceinline__ void ldsm4t(uint32_t* r, uint32_t addr) {
    asm volatile("ldmatrix.sync.aligned.m8n8.x4.trans.shared.b16 {%0,%1,%2,%3}, [%4];"
                 : "=r"(r[0]), "=r"(r[1]), "=r"(r[2]), "=r"(r[3]) : "r"(addr));
}
__device__ __forceinline__ void mma_f16(float* c, const uint32_t* a, const uint32_t* b) {
    asm volatile(
        "mma.sync.aligned.m16n8k16.row.col.f32.f16.f16.f32 "
        "{%0,%1,%2,%3}, {%4,%5,%6,%7}, {%8,%9}, {%0,%1,%2,%3};"
        : "+f"(c[0]), "+f"(c[1]), "+f"(c[2]), "+f"(c[3])
        : "r"(a[0]), "r"(a[1]), "r"(a[2]), "r"(a[3]), "r"(b[0]), "r"(b[1]));
}
__device__ __forceinline__ void cp16(uint32_t smem, const void* g) {
    asm volatile("cp.async.cg.shared.global [%0], [%1], 16;" :: "r"(smem), "l"(g));
}
#define CP_COMMIT() asm volatile("cp.async.commit_group;" ::: "memory")
#define CP_WAIT1()  asm volatile("cp.async.wait_group 1;" ::: "memory")
#define CP_WAIT0()  asm volatile("cp.async.wait_group 0;" ::: "memory")

__device__ __forceinline__ float fexp2(float x) {
    float r;
    asm("ex2.approx.f32 %0, %1;" : "=f"(r) : "f"(x));
    return r;
}
__device__ __forceinline__ uint32_t packh(float a, float b) {
    __half2 t = __floats2half2_rn(a, b);
    return *reinterpret_cast<uint32_t*>(&t);
}
__device__ __forceinline__ uint32_t packhlo(float a, float b, uint32_t hi) {
    __half2 h = *reinterpret_cast<__half2*>(&hi);
    float2 hf = __half22float2(h);
    return packh(a - hf.x, b - hf.y);
}
__device__ __forceinline__ uint32_t packbf(float a, float b) {
    __nv_bfloat162 t = __float22bfloat162_rn(make_float2(a, b));
    return *reinterpret_cast<uint32_t*>(&t);
}

// ---------------------------------------------------------------------------
// fused prepass: x hi/lo split (fp16) + both weight transposes (fp16 hi only)
// ---------------------------------------------------------------------------
#define BLK_SPLIT 32768
#define BLK_TQKV  3072
#define BLK_TWO   1024

__global__ __launch_bounds__(256)
void prepass_kernel(const float* __restrict__ x,
                    const float* __restrict__ Wqkv,
                    const float* __restrict__ Wout,
                    __half* __restrict__ xhi, __half* __restrict__ xlo,
                    __half* __restrict__ wqhi, __half* __restrict__ wohi)
{
    __shared__ float t[32][33];
    const int bid = blockIdx.x;
    const int tid = threadIdx.x;

    if (bid < BLK_SPLIT) {
        const int i = bid * 256 + tid;
        float v = x[i];
        __half h = __float2half_rn(v);
        xhi[i] = h;
        xlo[i] = __float2half_rn(v - __half2float(h));
        return;
    }

    const float* W;
    __half* Thi;
    int N, tb;
    if (bid < BLK_SPLIT + BLK_TQKV) {
        tb = bid - BLK_SPLIT; W = Wqkv; Thi = wqhi; N = 3 * ND;
    } else {
        tb = bid - BLK_SPLIT - BLK_TQKV; W = Wout; Thi = wohi; N = ND;
    }
    const int K = ND;
    const int n0 = (tb % (N / 32)) * 32;
    const int k0 = (tb / (N / 32)) * 32;
    const int tx = tid & 31, ty = tid >> 5;
    #pragma unroll
    for (int j = 0; j < 32; j += 8)
        t[ty + j][tx] = W[(size_t)(k0 + ty + j) * N + n0 + tx];
    __syncthreads();
    #pragma unroll
    for (int j = 0; j < 32; j += 8)
        Thi[(size_t)(n0 + ty + j) * K + k0 + tx] = __float2half_rn(t[tx][ty + j]);
}

// ---------------------------------------------------------------------------
// entity bias fp32 -> bf16 * log2(e)
// ---------------------------------------------------------------------------
__global__ __launch_bounds__(256)
void bias_to_bf16_kernel(const float* __restrict__ src, __nv_bfloat16* __restrict__ dst)
{
    const size_t i = ((size_t)blockIdx.x * 256 + threadIdx.x) * 4;
    const float4 v = *reinterpret_cast<const float4*>(src + i);
    uint32_t p0 = packbf(v.x * LOG2E, v.y * LOG2E);
    uint32_t p1 = packbf(v.z * LOG2E, v.w * LOG2E);
    *reinterpret_cast<uint32_t*>(dst + i)     = p0;
    *reinterpret_cast<uint32_t*>(dst + i + 2) = p1;
}

// ---------------------------------------------------------------------------
// fp16x2 GEMM: C = (A_hi+A_lo) @ B_hi^T + bias. 2 MMA passes per k-step.
// 256 thr, tile 128x128, BK=32, 2-stage pipeline, smem 61440 -> 2 CTAs/SM.
// MODE 0: fp32 out + bias. MODE 1: QKV epilogue (q hi+lo, k/v hi only).
// ---------------------------------------------------------------------------
#define STG_BYTES 30720
#define T_AHI 0
#define T_ALO 10240
#define T_BHI 20480

template <int MODE>
__global__ __launch_bounds__(256, 2)
void gemm_f16x2(const __half* __restrict__ Ahi, const __half* __restrict__ Alo,
                const __half* __restrict__ Bhi,
                const float* __restrict__ bias, float* __restrict__ C,
                __half* __restrict__ qhi, __half* __restrict__ qlo,
                __half* __restrict__ khi, __half* __restrict__ vhi,
                int M, int N, int K)
{
    extern __shared__ char dynsm[];
    const uint32_t sb0 = smem_u32(dynsm);

    const int tid = threadIdx.x;
    const int wid = tid >> 5;
    const int l   = tid & 31;
    const int wm  = wid >> 1;
    const int wn  = wid & 1;
    const size_t m0 = (size_t)blockIdx.y * 128;
    const size_t n0 = (size_t)blockIdx.x * 128;

    const int r1 = tid >> 2;
    const int r2 = r1 + 64;
    const int cc = (tid & 3);
    const uint32_t sm_off1 = (uint32_t)r1 * 80 + cc * 16;
    const uint32_t sm_off2 = (uint32_t)r2 * 80 + cc * 16;

    const int nchunks = K >> 5;

    auto issue_stage = [&](int c, int buf) {
        const int kc = c << 5;
        const uint32_t sb = sb0 + buf * STG_BYTES;
        cp16(sb + T_AHI + sm_off1, Ahi + (m0 + r1) * K + kc + cc * 8);
        cp16(sb + T_AHI + sm_off2, Ahi + (m0 + r2) * K + kc + cc * 8);
        cp16(sb + T_ALO + sm_off1, Alo + (m0 + r1) * K + kc + cc * 8);
        cp16(sb + T_ALO + sm_off2, Alo + (m0 + r2) * K + kc + cc * 8);
        cp16(sb + T_BHI + sm_off1, Bhi + (n0 + r1) * K + kc + cc * 8);
        cp16(sb + T_BHI + sm_off2, Bhi + (n0 + r2) * K + kc + cc * 8);
        CP_COMMIT();
    };

    const int aRow = (l & 7) + ((l >> 3) & 1) * 8;
    const int aCol8 = (l >> 4) * 8;
    const int bRow = (l & 7) + ((l >> 4) & 1) * 8;
    const int bCol8 = ((l >> 3) & 1) * 8;

    float acc[2][8][4];
    #pragma unroll
    for (int mt = 0; mt < 2; mt++)
        #pragma unroll
        for (int nt = 0; nt < 8; nt++)
            #pragma unroll
            for (int k = 0; k < 4; k++) acc[mt][nt][k] = 0.f;

    issue_stage(0, 0);

    for (int c = 0; c < nchunks; c++) {
        if (c + 1 < nchunks) {
            issue_stage(c + 1, (c + 1) & 1);
            CP_WAIT1();
        } else {
            CP_WAIT0();
        }
        __syncthreads();

        const uint32_t sb = sb0 + (c & 1) * STG_BYTES;
        const uint32_t aBase = sb + (uint32_t)(wm * 32 + aRow) * 80 + aCol8 * 2;
        const uint32_t bBase = sb + (uint32_t)(wn * 64 + bRow) * 80 + bCol8 * 2;

        #pragma unroll
        for (int ks = 0; ks < 2; ks++) {
            uint32_t ah[2][4], al4[2][4];
            #pragma unroll
            for (int mt = 0; mt < 2; mt++) {
                ldsm4(ah[mt],  aBase + T_AHI + mt * (16 * 80) + ks * 32);
                ldsm4(al4[mt], aBase + T_ALO + mt * (16 * 80) + ks * 32);
            }
            #pragma unroll
            for (int np = 0; np < 4; np++) {
                uint32_t bh[4];
                ldsm4(bh, bBase + T_BHI + np * (16 * 80) + ks * 32);
                #pragma unroll
                for (int mt = 0; mt < 2; mt++)
                    #pragma unroll
                    for (int sub = 0; sub < 2; sub++) {
                        const int nt = np * 2 + sub;
                        mma_f16(acc[mt][nt], ah[mt],  &bh[sub * 2]);
                        mma_f16(acc[mt][nt], al4[mt], &bh[sub * 2]);
                    }
            }
        }
        __syncthreads();
    }

    if (MODE == 0) {
        #pragma unroll
        for (int mt = 0; mt < 2; mt++) {
            const size_t row0 = m0 + wm * 32 + mt * 16 + (l >> 2);
            #pragma unroll
            for (int nt = 0; nt < 8; nt++) {
                const size_t col = n0 + wn * 64 + nt * 8 + (l & 3) * 2;
                const float b0 = bias[col], b1 = bias[col + 1];
                float2 v0 = { acc[mt][nt][0] + b0, acc[mt][nt][1] + b1 };
                float2 v1 = { acc[mt][nt][2] + b0, acc[mt][nt][3] + b1 };
                *reinterpret_cast<float2*>(&C[row0 * N + col]) = v0;
                *reinterpret_cast<float2*>(&C[(row0 + 8) * N + col]) = v1;
            }
        }
    } else {
        const int colbase = (int)n0 + wn * 64;
        const int sel = colbase >> 10;             // 0=q,1=k,2=v
        const int head = (colbase >> 6) & 15;
        const float qs = (sel == 0) ? QSCALE : 1.0f;
        __half* dh = (sel == 0) ? qhi : (sel == 1) ? khi : vhi;
        #pragma unroll
        for (int mt = 0; mt < 2; mt++) {
            const int row0 = (int)m0 + wm * 32 + mt * 16 + (l >> 2);
            const int bb = row0 >> 11;
            const int t0 = row0 & 2047;
            const size_t base = ((size_t)(bb * NH + head) * NT + t0) * NHD;
            #pragma unroll
            for (int nt = 0; nt < 8; nt++) {
                const int col = colbase + nt * 8 + (l & 3) * 2;
                const int d = col & 63;
                const float b0 = bias[col], b1 = bias[col + 1];
                const float v0 = (acc[mt][nt][0] + b0) * qs, v1 = (acc[mt][nt][1] + b1) * qs;
                const float v2 = (acc[mt][nt][2] + b0) * qs, v3 = (acc[mt][nt][3] + b1) * qs;
                const uint32_t h0 = packh(v0, v1);
                const uint32_t h1 = packh(v2, v3);
                *reinterpret_cast<uint32_t*>(dh + base + d)           = h0;
                *reinterpret_cast<uint32_t*>(dh + base + 8 * NHD + d) = h1;
                if (sel == 0) {
                    *reinterpret_cast<uint32_t*>(qlo + base + d)           = packhlo(v0, v1, h0);
                    *reinterpret_cast<uint32_t*>(qlo + base + 8 * NHD + d) = packhlo(v2, v3, h1);
                }
            }
        }
    }
}

// ---------------------------------------------------------------------------
// fp16x2 flash attention: Q (hi+lo, A-side) x K_hi; P (hi+lo) x V_hi.
// 128 threads, 4 warps, warp M=32, keytile 64, 2 CTAs/SM.
// smem: 2 x 18432 KV (Khi|Vhi) + 36864 Q = 73728 B.
// ---------------------------------------------------------------------------
#define FROWB 144
#define KVARR (64 * FROWB)            // 9216
#define KVBUF (2 * KVARR)             // 18432 : Khi|Vhi
#define QOFF (2 * KVBUF)              // 36864
#define QARR (128 * FROWB)            // 18432
#define FLASH_SMEM (QOFF + 2 * QARR)  // 73728

__global__ __launch_bounds__(128, 2)
void flash_mma(const __half* __restrict__ qhi, const __half* __restrict__ qlo,
               const __half* __restrict__ khi, const __half* __restrict__ vhi,
               const __nv_bfloat16* __restrict__ ebias,
               __half* __restrict__ out_hi, __half* __restrict__ out_lo)
{
    extern __shared__ char sm[];
    const uint32_t s0 = smem_u32(sm);
    const int tid = threadIdx.x, w = tid >> 5, l = tid & 31;
    const int qb = 15 - blockIdx.x;          // heavy CTAs first
    const int h = blockIdx.y, b = blockIdx.z;
    const int q0 = qb * 128;
    const size_t hoff = (size_t)(b * NH + h) * NT * NHD;
    const int ntiles = 2 * qb + 2;           // key tiles of 64

    auto issue_kv = [&](int jt2, int bsel2) {
        #pragma unroll
        for (int i = 0; i < 8; i++) {
            const int ck = tid + i * 128;            // 0..1023
            const int arr = ck >> 9;                 // 0=Khi, 1=Vhi
            const int row = (ck >> 3) & 63;
            const int seg = ck & 7;
            const size_t go = hoff + (size_t)(jt2 * 64 + row) * NHD + seg * 8;
            const __half* src = (arr == 0) ? khi + go : vhi + go;
            cp16(s0 + bsel2 * KVBUF + arr * KVARR + row * FROWB + seg * 16, src);
        }
        CP_COMMIT();
    };

    // prologue: Q (128 rows hi+lo) -> persistent region, KV(0) -> buf0
    #pragma unroll
    for (int i = 0; i < 16; i++) {
        const int cq = tid + i * 128;                // 0..2047
        const int arr = cq >> 10;                    // 0=hi,1=lo
        const int row = (cq >> 3) & 127;
        const int seg = cq & 7;
        const __half* src = (arr ? qlo : qhi) + hoff + (size_t)(q0 + row) * NHD + seg * 8;
        cp16(s0 + QOFF + arr * QARR + row * FROWB + seg * 16, src);
    }
    CP_COMMIT();
    issue_kv(0, 0);

    float O[2][8][4];
    #pragma unroll
    for (int mt = 0; mt < 2; mt++)
        #pragma unroll
        for (int nt = 0; nt < 8; nt++)
            #pragma unroll
            for (int k = 0; k < 4; k++) O[mt][nt][k] = 0.f;
    float ms[4] = {-INFINITY, -INFINITY, -INFINITY, -INFINITY};
    float ls[4] = {0.f, 0.f, 0.f, 0.f};

    int gq[4];
    #pragma unroll
    for (int i = 0; i < 4; i++) gq[i] = q0 + w * 32 + (i >> 1) * 16 + (i & 1) * 8 + (l >> 2);
    const int gq_max_warp = q0 + w * 32 + 31;
    const int warp_row0   = q0 + w * 32;

    const uint32_t nRow  = (uint32_t)((l & 7) + ((l >> 4) & 1) * 8);
    const uint32_t kColB = (uint32_t)(((l >> 3) & 1) * 16);
    const uint32_t vRowP = (uint32_t)((l & 7) + ((l >> 3) & 1) * 8);
    const uint32_t vColB = (uint32_t)(((l >> 4) & 1) * 16);
    const uint32_t qb0 = s0 + QOFF +
        (uint32_t)(w * 32 + (l & 7) + ((l >> 3) & 1) * 8) * FROWB + ((l >> 4) * 16);

    const __nv_bfloat16* biasp[4];
    #pragma unroll
    for (int i = 0; i < 4; i++)
        biasp[i] = ebias + ((size_t)b * NT + gq[i]) * NT + 2 * (l & 3);

    for (int jt = 0; jt < ntiles; jt++) {
        const int bsel = jt & 1;
        CP_WAIT0();
        __syncthreads();
        if (jt + 1 < ntiles) issue_kv(jt + 1, bsel ^ 1);

        if (jt * 64 > gq_max_warp) continue;

        // ---- S = Q K_hi^T (2 passes: Qhi + Qlo), K fragments shared by 2 m-tiles
        float acc[2][8][4];
        #pragma unroll
        for (int mt = 0; mt < 2; mt++)
            #pragma unroll
            for (int nt = 0; nt < 8; nt++)
                #pragma unroll
                for (int k = 0; k < 4; k++) acc[mt][nt][k] = 0.f;

        const uint32_t kb = s0 + bsel * KVBUF;
        #pragma unroll
        for (int ks = 0; ks < 4; ks++) {
            uint32_t qh0[4], ql0[4], qh1[4], ql1[4];
            const uint32_t qa = qb0 + ks * 32;
            ldsm4(qh0, qa);
            ldsm4(ql0, qa + QARR);
            ldsm4(qh1, qa + 16 * FROWB);
            ldsm4(ql1, qa + 16 * FROWB + QARR);
            #pragma unroll
            for (int np = 0; np < 4; np++) {
                uint32_t khf[4];
                ldsm4(khf, kb + (np * 16 + nRow) * FROWB + kColB + ks * 32);
                #pragma unroll
                for (int sub = 0; sub < 2; sub++) {
                    const int nt = np * 2 + sub;
                    mma_f16(acc[0][nt], qh0, &khf[sub * 2]);
                    mma_f16(acc[0][nt], ql0, &khf[sub * 2]);
                    mma_f16(acc[1][nt], qh1, &khf[sub * 2]);
                    mma_f16(acc[1][nt], ql1, &khf[sub * 2]);
                }
            }
        }

        // ---- softmax per m-tile (log2 domain)
        const bool maskw = (jt * 64 + 63 > warp_row0);
        #pragma unroll
        for (int mt = 0; mt < 2; mt++) {
            uint32_t breg[16];
            #pragma unroll
            for (int nt = 0; nt < 8; nt++) {
                breg[nt]     = *reinterpret_cast<const uint32_t*>(biasp[mt * 2]     + jt * 64 + nt * 8);
                breg[8 + nt] = *reinterpret_cast<const uint32_t*>(biasp[mt * 2 + 1] + jt * 64 + nt * 8);
            }
            float mx0 = -INFINITY, mx1 = -INFINITY;
            #pragma unroll
            for (int nt = 0; nt < 8; nt++) {
                float2 bv0 = __bfloat1622float2(*reinterpret_cast<__nv_bfloat162*>(&breg[nt]));
                float2 bv1 = __bfloat1622float2(*reinterpret_cast<__nv_bfloat162*>(&breg[8 + nt]));
                float v0 = acc[mt][nt][0] + bv0.x;
                float v1 = acc[mt][nt][1] + bv0.y;
                float v2 = acc[mt][nt][2] + bv1.x;
                float v3 = acc[mt][nt][3] + bv1.y;
                if (maskw) {
                    const int kc = jt * 64 + nt * 8 + 2 * (l & 3);
                    if (kc > gq[mt * 2])         v0 = -1e30f;
                    if (kc + 1 > gq[mt * 2])     v1 = -1e30f;
                    if (kc > gq[mt * 2 + 1])     v2 = -1e30f;
                    if (kc + 1 > gq[mt * 2 + 1]) v3 = -1e30f;
                }
                acc[mt][nt][0] = v0; acc[mt][nt][1] = v1;
                acc[mt][nt][2] = v2; acc[mt][nt][3] = v3;
                mx0 = fmaxf(mx0, fmaxf(v0, v1));
                mx1 = fmaxf(mx1, fmaxf(v2, v3));
            }
            mx0 = fmaxf(mx0, __shfl_xor_sync(0xffffffff, mx0, 1));
            mx0 = fmaxf(mx0, __shfl_xor_sync(0xffffffff, mx0, 2));
            mx1 = fmaxf(mx1, __shfl_xor_sync(0xffffffff, mx1, 1));
            mx1 = fmaxf(mx1, __shfl_xor_sync(0xffffffff, mx1, 2));

            const float mn0 = fmaxf(ms[mt * 2], mx0), mn1 = fmaxf(ms[mt * 2 + 1], mx1);
            const float c0 = fexp2(ms[mt * 2] - mn0), c1 = fexp2(ms[mt * 2 + 1] - mn1);
            float rs0 = 0.f, rs1 = 0.f;
            #pragma unroll
            for (int nt = 0; nt < 8; nt++) {
                const float p0 = fexp2(acc[mt][nt][0] - mn0);
                const float p1 = fexp2(acc[mt][nt][1] - mn0);
                const float p2 = fexp2(acc[mt][nt][2] - mn1);
                const float p3 = fexp2(acc[mt][nt][3] - mn1);
                acc[mt][nt][0] = p0; acc[mt][nt][1] = p1;
                acc[mt][nt][2] = p2; acc[mt][nt][3] = p3;
                rs0 += p0 + p1;
                rs1 += p2 + p3;
            }
            rs0 += __shfl_xor_sync(0xffffffff, rs0, 1);
            rs0 += __shfl_xor_sync(0xffffffff, rs0, 2);
            rs1 += __shfl_xor_sync(0xffffffff, rs1, 1);
            rs1 += __shfl_xor_sync(0xffffffff, rs1, 2);
            ls[mt * 2]     = ls[mt * 2] * c0 + rs0;
            ls[mt * 2 + 1] = ls[mt * 2 + 1] * c1 + rs1;
            ms[mt * 2]     = mn0;
            ms[mt * 2 + 1] = mn1;
            #pragma unroll
            for (int nt = 0; nt < 8; nt++) {
                O[mt][nt][0] *= c0; O[mt][nt][1] *= c0;
                O[mt][nt][2] *= c1; O[mt][nt][3] *= c1;
            }
        }

        // ---- O += P V_hi (2 passes: Phi + Plo), V fragments shared by 2 m-tiles
        const uint32_t vb = kb + KVARR;
        #pragma unroll
        for (int kk = 0; kk < 4; kk++) {
            uint32_t phi0[4], plo0[4], phi1[4], plo1[4];
            phi0[0] = packh(acc[0][2 * kk][0], acc[0][2 * kk][1]);
            plo0[0] = packhlo(acc[0][2 * kk][0], acc[0][2 * kk][1], phi0[0]);
            phi0[1] = packh(acc[0][2 * kk][2], acc[0][2 * kk][3]);
            plo0[1] = packhlo(acc[0][2 * kk][2], acc[0][2 * kk][3], phi0[1]);
            phi0[2] = packh(acc[0][2 * kk + 1][0], acc[0][2 * kk + 1][1]);
            plo0[2] = packhlo(acc[0][2 * kk + 1][0], acc[0][2 * kk + 1][1], phi0[2]);
            phi0[3] = packh(acc[0][2 * kk + 1][2], acc[0][2 * kk + 1][3]);
            plo0[3] = packhlo(acc[0][2 * kk + 1][2], acc[0][2 * kk + 1][3], phi0[3]);
            phi1[0] = packh(acc[1][2 * kk][0], acc[1][2 * kk][1]);
            plo1[0] = packhlo(acc[1][2 * kk][0], acc[1][2 * kk][1], phi1[0]);
            phi1[1] = packh(acc[1][2 * kk][2], acc[1][2 * kk][3]);
            plo1[1] = packhlo(acc[1][2 * kk][2], acc[1][2 * kk][3], phi1[1]);
            phi1[2] = packh(acc[1][2 * kk + 1][0], acc[1][2 * kk + 1][1]);
            plo1[2] = packhlo(acc[1][2 * kk + 1][0], acc[1][2 * kk + 1][1], phi1[2]);
            phi1[3] = packh(acc[1][2 * kk + 1][2], acc[1][2 * kk + 1][3]);
            plo1[3] = packhlo(acc[1][2 * kk + 1][2], acc[1][2 * kk + 1][3], phi1[3]);
            #pragma unroll
            for (int nn = 0; nn < 4; nn++) {
                uint32_t vhf[4];
                ldsm4t(vhf, vb + (kk * 16 + vRowP) * FROWB + nn * 32 + vColB);
                #pragma unroll
                for (int sub = 0; sub < 2; sub++) {
                    const int nt = nn * 2 + sub;
                    mma_f16(O[0][nt], phi0, &vhf[sub * 2]);
                    mma_f16(O[0][nt], plo0, &vhf[sub * 2]);
                    mma_f16(O[1][nt], phi1, &vhf[sub * 2]);
                    mma_f16(O[1][nt], plo1, &vhf[sub * 2]);
                }
            }
        }
    }

    // ---- epilogue: O/l -> fp16 hi/lo, [B,T,D] layout
    #pragma unroll
    for (int mt = 0; mt < 2; mt++) {
        const float inv0 = 1.f / ls[mt * 2], inv1 = 1.f / ls[mt * 2 + 1];
        const size_t a0 = ((size_t)b * NT + gq[mt * 2])     * ND + h * NHD + 2 * (l & 3);
        const size_t a1 = ((size_t)b * NT + gq[mt * 2 + 1]) * ND + h * NHD + 2 * (l & 3);
        #pragma unroll
        for (int nt = 0; nt < 8; nt++) {
            const float o0 = O[mt][nt][0] * inv0, o1 = O[mt][nt][1] * inv0;
            const float o2 = O[mt][nt][2] * inv1, o3 = O[mt][nt][3] * inv1;
            const uint32_t h0 = packh(o0, o1), lo0 = packhlo(o0, o1, h0);
            const uint32_t h1 = packh(o2, o3), lo1 = packhlo(o2, o3, h1);
            *reinterpret_cast<uint32_t*>(out_hi + a0 + nt * 8) = h0;
            *reinterpret_cast<uint32_t*>(out_lo + a0 + nt * 8) = lo0;
            *reinterpret_cast<uint32_t*>(out_hi + a1 + nt * 8) = h1;
            *reinterpret_cast<uint32_t*>(out_lo + a1 + nt * 8) = lo1;
        }
    }
}

// ---------------------------------------------------------------------------
extern "C" void kernel_launch(void* const* d_in, const int* in_sizes, int n_in,
                              void* d_out, int out_size)
{
    const float* x     = (const float*)d_in[0];
    const float* eb    = (const float*)d_in[1];
    const float* Wqkv  = (const float*)d_in[2];
    const float* bqkv  = (const float*)d_in[3];
    const float* Wout  = (const float*)d_in[4];
    const float* bout  = (const float*)d_in[5];
    float* out = (float*)d_out;

    __half *xhi, *xlo, *wqhi, *wohi, *athi, *atlo;
    __half *qhi, *qlo, *khi2, *vhi2;
    __nv_bfloat16* ebbf;
    cudaGetSymbolAddress((void**)&xhi,  g_x_hi);
    cudaGetSymbolAddress((void**)&xlo,  g_x_lo);
    cudaGetSymbolAddress((void**)&wqhi, g_wq_hi);
    cudaGetSymbolAddress((void**)&wohi, g_wo_hi);
    cudaGetSymbolAddress((void**)&athi, g_att_hi);
    cudaGetSymbolAddress((void**)&atlo, g_att_lo);
    cudaGetSymbolAddress((void**)&qhi,  g_q_hi);
    cudaGetSymbolAddress((void**)&qlo,  g_q_lo);
    cudaGetSymbolAddress((void**)&khi2, g_k_hi);
    cudaGetSymbolAddress((void**)&vhi2, g_v_hi);
    cudaGetSymbolAddress((void**)&ebbf, g_eb_bf);

    const int M = NB * NT;   // 8192

    // [0] fused prepass
    prepass_kernel<<<BLK_SPLIT + BLK_TQKV + BLK_TWO, 256>>>(
        x, Wqkv, Wout, xhi, xlo, wqhi, wohi);

    // [1] bias -> bf16 (pre-scaled by log2e)
    bias_to_bf16_kernel<<<(int)(((size_t)NB * NT * NT) / 4 / 256), 256>>>(eb, ebbf);

    const int gemm_smem = 2 * STG_BYTES;   // 61440 -> 2 CTAs/SM
    cudaFuncSetAttribute(gemm_f16x2<0>, cudaFuncAttributeMaxDynamicSharedMemorySize, gemm_smem);
    cudaFuncSetAttribute(gemm_f16x2<1>, cudaFuncAttributeMaxDynamicSharedMemorySize, gemm_smem);

    // [2] QKV projection (2-pass fp16), fused per-head split epilogue
    gemm_f16x2<1><<<dim3(3 * ND / 128, M / 128), 256, gemm_smem>>>(
        xhi, xlo, wqhi, bqkv, nullptr,
        qhi, qlo, khi2, vhi2, M, 3 * ND, ND);

    // [3] flash attention (fp16x2)  <-- ncu profile index 3
    cudaFuncSetAttribute(flash_mma, cudaFuncAttributeMaxDynamicSharedMemorySize, FLASH_SMEM);
    flash_mma<<<dim3(NT / 128, NH, NB), 128, FLASH_SMEM>>>(
        qhi, qlo, khi2, vhi2, ebbf, athi, atlo);

    // [4] output projection (2-pass fp16, fp32 out + bias)
    gemm_f16x2<0><<<dim3(ND / 128, M / 128), 256, gemm_smem>>>(
        athi, atlo, wohi, bout, out,
        nullptr, nullptr, nullptr, nullptr, M, ND, ND);
}

// round 13
// speedup vs baseline: 2.0497x; 1.4527x over previous
#include <cuda_runtime.h>
#include <cuda_fp16.h>
#include <cuda_bf16.h>
#include <math.h>
#include <stdint.h>

#define NB 4
#define NT 2048
#define ND 1024
#define NH 16
#define NHD 64

#define QSCALE 0.1803368801111244f   // 0.125 * log2(e)
#define LOG2E  1.4426950408889634f

// ---------------------------------------------------------------------------
// scratch (allocation-free rule: __device__ globals) — plain fp16 everywhere
// ---------------------------------------------------------------------------
__device__ __align__(256) __half g_x_h[(size_t)NB * NT * ND];
__device__ __align__(256) __half g_wq_h[(size_t)3 * ND * ND];     // Wqkv^T [3D, D]
__device__ __align__(256) __half g_wo_h[(size_t)ND * ND];         // Wout^T [D, D]
__device__ __align__(256) __half g_att_h[(size_t)NB * NT * ND];
// per-head q/k/v: [B,H,T,64] fp16 (q pre-scaled by QSCALE)
__device__ __align__(256) __half g_q_h[(size_t)NB * NH * NT * NHD];
__device__ __align__(256) __half g_k_h[(size_t)NB * NH * NT * NHD];
__device__ __align__(256) __half g_v_h[(size_t)NB * NH * NT * NHD];
// entity bias in bf16, pre-multiplied by log2(e)
__device__ __align__(256) __nv_bfloat16 g_eb_bf[(size_t)NB * NT * NT];

// ---------------------------------------------------------------------------
// PTX helpers (all baseline sm_80+)
// ---------------------------------------------------------------------------
__device__ __forceinline__ uint32_t smem_u32(const void* p) {
    uint32_t a;
    asm("{ .reg .u64 t; cvta.to.shared.u64 t, %1; cvt.u32.u64 %0, t; }" : "=r"(a) : "l"(p));
    return a;
}
__device__ __forceinline__ void ldsm4(uint32_t* r, uint32_t addr) {
    asm volatile("ldmatrix.sync.aligned.m8n8.x4.shared.b16 {%0,%1,%2,%3}, [%4];"
                 : "=r"(r[0]), "=r"(r[1]), "=r"(r[2]), "=r"(r[3]) : "r"(addr));
}
__device__ __forceinline__ void ldsm4t(uint32_t* r, uint32_t addr) {
    asm volatile("ldmatrix.sync.aligned.m8n8.x4.trans.shared.b16 {%0,%1,%2,%3}, [%4];"
                 : "=r"(r[0]), "=r"(r[1]), "=r"(r[2]), "=r"(r[3]) : "r"(addr));
}
__device__ __forceinline__ void mma_f16(float* c, const uint32_t* a, const uint32_t* b) {
    asm volatile(
        "mma.sync.aligned.m16n8k16.row.col.f32.f16.f16.f32 "
        "{%0,%1,%2,%3}, {%4,%5,%6,%7}, {%8,%9}, {%0,%1,%2,%3};"
        : "+f"(c[0]), "+f"(c[1]), "+f"(c[2]), "+f"(c[3])
        : "r"(a[0]), "r"(a[1]), "r"(a[2]), "r"(a[3]), "r"(b[0]), "r"(b[1]));
}
__device__ __forceinline__ void cp16(uint32_t smem, const void* g) {
    asm volatile("cp.async.cg.shared.global [%0], [%1], 16;" :: "r"(smem), "l"(g));
}
#define CP_COMMIT() asm volatile("cp.async.commit_group;" ::: "memory")
#define CP_WAIT1()  asm volatile("cp.async.wait_group 1;" ::: "memory")
#define CP_WAIT0()  asm volatile("cp.async.wait_group 0;" ::: "memory")

__device__ __forceinline__ float fexp2(float x) {
    float r;
    asm("ex2.approx.f32 %0, %1;" : "=f"(r) : "f"(x));
    return r;
}
__device__ __forceinline__ uint32_t packh(float a, float b) {
    __half2 t = __floats2half2_rn(a, b);
    return *reinterpret_cast<uint32_t*>(&t);
}
__device__ __forceinline__ uint32_t packbf(float a, float b) {
    __nv_bfloat162 t = __float22bfloat162_rn(make_float2(a, b));
    return *reinterpret_cast<uint32_t*>(&t);
}

// ---------------------------------------------------------------------------
// fused prepass: x -> fp16 + both weight transposes (fp16)
// ---------------------------------------------------------------------------
#define BLK_SPLIT 32768
#define BLK_TQKV  3072
#define BLK_TWO   1024

__global__ __launch_bounds__(256)
void prepass_kernel(const float* __restrict__ x,
                    const float* __restrict__ Wqkv,
                    const float* __restrict__ Wout,
                    __half* __restrict__ xh,
                    __half* __restrict__ wqh, __half* __restrict__ woh)
{
    __shared__ float t[32][33];
    const int bid = blockIdx.x;
    const int tid = threadIdx.x;

    if (bid < BLK_SPLIT) {
        const int i = bid * 256 + tid;
        xh[i] = __float2half_rn(x[i]);
        return;
    }

    const float* W;
    __half* Th;
    int N, tb;
    if (bid < BLK_SPLIT + BLK_TQKV) {
        tb = bid - BLK_SPLIT; W = Wqkv; Th = wqh; N = 3 * ND;
    } else {
        tb = bid - BLK_SPLIT - BLK_TQKV; W = Wout; Th = woh; N = ND;
    }
    const int K = ND;
    const int n0 = (tb % (N / 32)) * 32;
    const int k0 = (tb / (N / 32)) * 32;
    const int tx = tid & 31, ty = tid >> 5;
    #pragma unroll
    for (int j = 0; j < 32; j += 8)
        t[ty + j][tx] = W[(size_t)(k0 + ty + j) * N + n0 + tx];
    __syncthreads();
    #pragma unroll
    for (int j = 0; j < 32; j += 8)
        Th[(size_t)(n0 + ty + j) * K + k0 + tx] = __float2half_rn(t[tx][ty + j]);
}

// ---------------------------------------------------------------------------
// entity bias fp32 -> bf16 * log2(e)
// ---------------------------------------------------------------------------
__global__ __launch_bounds__(256)
void bias_to_bf16_kernel(const float* __restrict__ src, __nv_bfloat16* __restrict__ dst)
{
    const size_t i = ((size_t)blockIdx.x * 256 + threadIdx.x) * 4;
    const float4 v = *reinterpret_cast<const float4*>(src + i);
    uint32_t p0 = packbf(v.x * LOG2E, v.y * LOG2E);
    uint32_t p1 = packbf(v.z * LOG2E, v.w * LOG2E);
    *reinterpret_cast<uint32_t*>(dst + i)     = p0;
    *reinterpret_cast<uint32_t*>(dst + i + 2) = p1;
}

// ---------------------------------------------------------------------------
// fp16 GEMM (1 pass): C = A @ B^T + bias. 256 thr, tile 128x128, BK=32,
// 3-stage cp.async pipeline (20480 B/stage, 61440 total) -> 2 CTAs/SM.
// MODE 0: fp32 out + bias. MODE 1: QKV epilogue -> per-head q/k/v fp16.
// ---------------------------------------------------------------------------
#define STG_BYTES 20480
#define T_AH 0
#define T_BH 10240

template <int MODE>
__global__ __launch_bounds__(256, 2)
void gemm_f16(const __half* __restrict__ Ah, const __half* __restrict__ Bh,
              const float* __restrict__ bias, float* __restrict__ C,
              __half* __restrict__ qh, __half* __restrict__ kh, __half* __restrict__ vh,
              int M, int N, int K)
{
    extern __shared__ char dynsm[];
    const uint32_t sb0 = smem_u32(dynsm);

    const int tid = threadIdx.x;
    const int wid = tid >> 5;
    const int l   = tid & 31;
    const int wm  = wid >> 1;
    const int wn  = wid & 1;
    const size_t m0 = (size_t)blockIdx.y * 128;
    const size_t n0 = (size_t)blockIdx.x * 128;

    const int r1 = tid >> 2;
    const int r2 = r1 + 64;
    const int cc = (tid & 3);
    const uint32_t sm_off1 = (uint32_t)r1 * 80 + cc * 16;
    const uint32_t sm_off2 = (uint32_t)r2 * 80 + cc * 16;

    const int nchunks = K >> 5;

    auto issue_stage = [&](int c, int buf) {
        const int kc = c << 5;
        const uint32_t sb = sb0 + buf * STG_BYTES;
        cp16(sb + T_AH + sm_off1, Ah + (m0 + r1) * K + kc + cc * 8);
        cp16(sb + T_AH + sm_off2, Ah + (m0 + r2) * K + kc + cc * 8);
        cp16(sb + T_BH + sm_off1, Bh + (n0 + r1) * K + kc + cc * 8);
        cp16(sb + T_BH + sm_off2, Bh + (n0 + r2) * K + kc + cc * 8);
        CP_COMMIT();
    };

    const int aRow = (l & 7) + ((l >> 3) & 1) * 8;
    const int aCol8 = (l >> 4) * 8;
    const int bRow = (l & 7) + ((l >> 4) & 1) * 8;
    const int bCol8 = ((l >> 3) & 1) * 8;

    float acc[2][8][4];
    #pragma unroll
    for (int mt = 0; mt < 2; mt++)
        #pragma unroll
        for (int nt = 0; nt < 8; nt++)
            #pragma unroll
            for (int k = 0; k < 4; k++) acc[mt][nt][k] = 0.f;

    issue_stage(0, 0);
    issue_stage(1, 1);

    for (int c = 0; c < nchunks; c++) {
        if (c == nchunks - 1) { CP_WAIT0(); } else { CP_WAIT1(); }
        __syncthreads();
        if (c + 2 < nchunks) issue_stage(c + 2, (c + 2) % 3);

        const uint32_t sb = sb0 + (c % 3) * STG_BYTES;
        const uint32_t aBase = sb + (uint32_t)(wm * 32 + aRow) * 80 + aCol8 * 2;
        const uint32_t bBase = sb + (uint32_t)(wn * 64 + bRow) * 80 + bCol8 * 2;

        #pragma unroll
        for (int ks = 0; ks < 2; ks++) {
            uint32_t ah[2][4];
            #pragma unroll
            for (int mt = 0; mt < 2; mt++)
                ldsm4(ah[mt], aBase + T_AH + mt * (16 * 80) + ks * 32);
            #pragma unroll
            for (int np = 0; np < 4; np++) {
                uint32_t bh[4];
                ldsm4(bh, bBase + T_BH + np * (16 * 80) + ks * 32);
                #pragma unroll
                for (int mt = 0; mt < 2; mt++)
                    #pragma unroll
                    for (int sub = 0; sub < 2; sub++)
                        mma_f16(acc[mt][np * 2 + sub], ah[mt], &bh[sub * 2]);
            }
        }
        __syncthreads();
    }

    if (MODE == 0) {
        #pragma unroll
        for (int mt = 0; mt < 2; mt++) {
            const size_t row0 = m0 + wm * 32 + mt * 16 + (l >> 2);
            #pragma unroll
            for (int nt = 0; nt < 8; nt++) {
                const size_t col = n0 + wn * 64 + nt * 8 + (l & 3) * 2;
                const float b0 = bias[col], b1 = bias[col + 1];
                float2 v0 = { acc[mt][nt][0] + b0, acc[mt][nt][1] + b1 };
                float2 v1 = { acc[mt][nt][2] + b0, acc[mt][nt][3] + b1 };
                *reinterpret_cast<float2*>(&C[row0 * N + col]) = v0;
                *reinterpret_cast<float2*>(&C[(row0 + 8) * N + col]) = v1;
            }
        }
    } else {
        const int colbase = (int)n0 + wn * 64;
        const int sel = colbase >> 10;             // 0=q,1=k,2=v
        const int head = (colbase >> 6) & 15;
        const float qs = (sel == 0) ? QSCALE : 1.0f;
        __half* dh = (sel == 0) ? qh : (sel == 1) ? kh : vh;
        #pragma unroll
        for (int mt = 0; mt < 2; mt++) {
            const int row0 = (int)m0 + wm * 32 + mt * 16 + (l >> 2);
            const int bb = row0 >> 11;
            const int t0 = row0 & 2047;
            const size_t base = ((size_t)(bb * NH + head) * NT + t0) * NHD;
            #pragma unroll
            for (int nt = 0; nt < 8; nt++) {
                const int col = colbase + nt * 8 + (l & 3) * 2;
                const int d = col & 63;
                const float b0 = bias[col], b1 = bias[col + 1];
                *reinterpret_cast<uint32_t*>(dh + base + d) =
                    packh((acc[mt][nt][0] + b0) * qs, (acc[mt][nt][1] + b1) * qs);
                *reinterpret_cast<uint32_t*>(dh + base + 8 * NHD + d) =
                    packh((acc[mt][nt][2] + b0) * qs, (acc[mt][nt][3] + b1) * qs);
            }
        }
    }
}

// ---------------------------------------------------------------------------
// fp16 flash attention (1-pass QK, 1-pass PV).
// 128 threads, 4 warps, warp M=32, keytile 64, 2 CTAs/SM.
// smem: 2 x 18432 KV (Kh|Vh) + 18432 Q = 55296 B.
// ---------------------------------------------------------------------------
#define FROWB 144
#define KVARR (64 * FROWB)            // 9216
#define KVBUF (2 * KVARR)             // 18432 : Kh|Vh
#define QOFF (2 * KVBUF)              // 36864
#define QARR (128 * FROWB)            // 18432
#define FLASH_SMEM (QOFF + QARR)      // 55296

__global__ __launch_bounds__(128, 2)
void flash_mma(const __half* __restrict__ qh, const __half* __restrict__ kh,
               const __half* __restrict__ vh,
               const __nv_bfloat16* __restrict__ ebias,
               __half* __restrict__ outp)
{
    extern __shared__ char sm[];
    const uint32_t s0 = smem_u32(sm);
    const int tid = threadIdx.x, w = tid >> 5, l = tid & 31;
    const int qb = 15 - blockIdx.x;          // heavy CTAs first
    const int h = blockIdx.y, b = blockIdx.z;
    const int q0 = qb * 128;
    const size_t hoff = (size_t)(b * NH + h) * NT * NHD;
    const int ntiles = 2 * qb + 2;           // key tiles of 64

    auto issue_kv = [&](int jt2, int bsel2) {
        #pragma unroll
        for (int i = 0; i < 8; i++) {
            const int ck = tid + i * 128;            // 0..1023
            const int arr = ck >> 9;                 // 0=Kh, 1=Vh
            const int row = (ck >> 3) & 63;
            const int seg = ck & 7;
            const size_t go = hoff + (size_t)(jt2 * 64 + row) * NHD + seg * 8;
            const __half* src = (arr == 0) ? kh + go : vh + go;
            cp16(s0 + bsel2 * KVBUF + arr * KVARR + row * FROWB + seg * 16, src);
        }
        CP_COMMIT();
    };

    // prologue: Q (128 rows) -> persistent region, KV(0) -> buf0
    #pragma unroll
    for (int i = 0; i < 8; i++) {
        const int cq = tid + i * 128;                // 0..1023
        const int row = cq >> 3;
        const int seg = cq & 7;
        cp16(s0 + QOFF + row * FROWB + seg * 16,
             qh + hoff + (size_t)(q0 + row) * NHD + seg * 8);
    }
    CP_COMMIT();
    issue_kv(0, 0);

    float O[2][8][4];
    #pragma unroll
    for (int mt = 0; mt < 2; mt++)
        #pragma unroll
        for (int nt = 0; nt < 8; nt++)
            #pragma unroll
            for (int k = 0; k < 4; k++) O[mt][nt][k] = 0.f;
    float ms[4] = {-INFINITY, -INFINITY, -INFINITY, -INFINITY};
    float ls[4] = {0.f, 0.f, 0.f, 0.f};

    int gq[4];
    #pragma unroll
    for (int i = 0; i < 4; i++) gq[i] = q0 + w * 32 + (i >> 1) * 16 + (i & 1) * 8 + (l >> 2);
    const int gq_max_warp = q0 + w * 32 + 31;
    const int warp_row0   = q0 + w * 32;

    const uint32_t nRow  = (uint32_t)((l & 7) + ((l >> 4) & 1) * 8);
    const uint32_t kColB = (uint32_t)(((l >> 3) & 1) * 16);
    const uint32_t vRowP = (uint32_t)((l & 7) + ((l >> 3) & 1) * 8);
    const uint32_t vColB = (uint32_t)(((l >> 4) & 1) * 16);
    const uint32_t qb0 = s0 + QOFF +
        (uint32_t)(w * 32 + (l & 7) + ((l >> 3) & 1) * 8) * FROWB + ((l >> 4) * 16);

    const __nv_bfloat16* biasp[4];
    #pragma unroll
    for (int i = 0; i < 4; i++)
        biasp[i] = ebias + ((size_t)b * NT + gq[i]) * NT + 2 * (l & 3);

    for (int jt = 0; jt < ntiles; jt++) {
        const int bsel = jt & 1;
        CP_WAIT0();
        __syncthreads();
        if (jt + 1 < ntiles) issue_kv(jt + 1, bsel ^ 1);

        if (jt * 64 > gq_max_warp) continue;

        // ---- S = Q K^T (1 pass), K fragments shared by 2 m-tiles
        float acc[2][8][4];
        #pragma unroll
        for (int mt = 0; mt < 2; mt++)
            #pragma unroll
            for (int nt = 0; nt < 8; nt++)
                #pragma unroll
                for (int k = 0; k < 4; k++) acc[mt][nt][k] = 0.f;

        const uint32_t kb = s0 + bsel * KVBUF;
        #pragma unroll
        for (int ks = 0; ks < 4; ks++) {
            uint32_t qf0[4], qf1[4];
            const uint32_t qa = qb0 + ks * 32;
            ldsm4(qf0, qa);
            ldsm4(qf1, qa + 16 * FROWB);
            #pragma unroll
            for (int np = 0; np < 4; np++) {
                uint32_t khf[4];
                ldsm4(khf, kb + (np * 16 + nRow) * FROWB + kColB + ks * 32);
                #pragma unroll
                for (int sub = 0; sub < 2; sub++) {
                    const int nt = np * 2 + sub;
                    mma_f16(acc[0][nt], qf0, &khf[sub * 2]);
                    mma_f16(acc[1][nt], qf1, &khf[sub * 2]);
                }
            }
        }

        // ---- softmax per m-tile (log2 domain)
        const bool maskw = (jt * 64 + 63 > warp_row0);
        #pragma unroll
        for (int mt = 0; mt < 2; mt++) {
            uint32_t breg[16];
            #pragma unroll
            for (int nt = 0; nt < 8; nt++) {
                breg[nt]     = *reinterpret_cast<const uint32_t*>(biasp[mt * 2]     + jt * 64 + nt * 8);
                breg[8 + nt] = *reinterpret_cast<const uint32_t*>(biasp[mt * 2 + 1] + jt * 64 + nt * 8);
            }
            float mx0 = -INFINITY, mx1 = -INFINITY;
            #pragma unroll
            for (int nt = 0; nt < 8; nt++) {
                float2 bv0 = __bfloat1622float2(*reinterpret_cast<__nv_bfloat162*>(&breg[nt]));
                float2 bv1 = __bfloat1622float2(*reinterpret_cast<__nv_bfloat162*>(&breg[8 + nt]));
                float v0 = acc[mt][nt][0] + bv0.x;
                float v1 = acc[mt][nt][1] + bv0.y;
                float v2 = acc[mt][nt][2] + bv1.x;
                float v3 = acc[mt][nt][3] + bv1.y;
                if (maskw) {
                    const int kc = jt * 64 + nt * 8 + 2 * (l & 3);
                    if (kc > gq[mt * 2])         v0 = -1e30f;
                    if (kc + 1 > gq[mt * 2])     v1 = -1e30f;
                    if (kc > gq[mt * 2 + 1])     v2 = -1e30f;
                    if (kc + 1 > gq[mt * 2 + 1]) v3 = -1e30f;
                }
                acc[mt][nt][0] = v0; acc[mt][nt][1] = v1;
                acc[mt][nt][2] = v2; acc[mt][nt][3] = v3;
                mx0 = fmaxf(mx0, fmaxf(v0, v1));
                mx1 = fmaxf(mx1, fmaxf(v2, v3));
            }
            mx0 = fmaxf(mx0, __shfl_xor_sync(0xffffffff, mx0, 1));
            mx0 = fmaxf(mx0, __shfl_xor_sync(0xffffffff, mx0, 2));
            mx1 = fmaxf(mx1, __shfl_xor_sync(0xffffffff, mx1, 1));
            mx1 = fmaxf(mx1, __shfl_xor_sync(0xffffffff, mx1, 2));

            const float mn0 = fmaxf(ms[mt * 2], mx0), mn1 = fmaxf(ms[mt * 2 + 1], mx1);
            const float c0 = fexp2(ms[mt * 2] - mn0), c1 = fexp2(ms[mt * 2 + 1] - mn1);
            float rs0 = 0.f, rs1 = 0.f;
            #pragma unroll
            for (int nt = 0; nt < 8; nt++) {
                const float p0 = fexp2(acc[mt][nt][0] - mn0);
                const float p1 = fexp2(acc[mt][nt][1] - mn0);
                const float p2 = fexp2(acc[mt][nt][2] - mn1);
                const float p3 = fexp2(acc[mt][nt][3] - mn1);
                acc[mt][nt][0] = p0; acc[mt][nt][1] = p1;
                acc[mt][nt][2] = p2; acc[mt][nt][3] = p3;
                rs0 += p0 + p1;
                rs1 += p2 + p3;
            }
            rs0 += __shfl_xor_sync(0xffffffff, rs0, 1);
            rs0 += __shfl_xor_sync(0xffffffff, rs0, 2);
            rs1 += __shfl_xor_sync(0xffffffff, rs1, 1);
            rs1 += __shfl_xor_sync(0xffffffff, rs1, 2);
            ls[mt * 2]     = ls[mt * 2] * c0 + rs0;
            ls[mt * 2 + 1] = ls[mt * 2 + 1] * c1 + rs1;
            ms[mt * 2]     = mn0;
            ms[mt * 2 + 1] = mn1;
            #pragma unroll
            for (int nt = 0; nt < 8; nt++) {
                O[mt][nt][0] *= c0; O[mt][nt][1] *= c0;
                O[mt][nt][2] *= c1; O[mt][nt][3] *= c1;
            }
        }

        // ---- O += P V (1 pass), V fragments shared by 2 m-tiles
        const uint32_t vb = kb + KVARR;
        #pragma unroll
        for (int kk = 0; kk < 4; kk++) {
            uint32_t p0[4], p1[4];
            p0[0] = packh(acc[0][2 * kk][0], acc[0][2 * kk][1]);
            p0[1] = packh(acc[0][2 * kk][2], acc[0][2 * kk][3]);
            p0[2] = packh(acc[0][2 * kk + 1][0], acc[0][2 * kk + 1][1]);
            p0[3] = packh(acc[0][2 * kk + 1][2], acc[0][2 * kk + 1][3]);
            p1[0] = packh(acc[1][2 * kk][0], acc[1][2 * kk][1]);
            p1[1] = packh(acc[1][2 * kk][2], acc[1][2 * kk][3]);
            p1[2] = packh(acc[1][2 * kk + 1][0], acc[1][2 * kk + 1][1]);
            p1[3] = packh(acc[1][2 * kk + 1][2], acc[1][2 * kk + 1][3]);
            #pragma unroll
            for (int nn = 0; nn < 4; nn++) {
                uint32_t vhf[4];
                ldsm4t(vhf, vb + (kk * 16 + vRowP) * FROWB + nn * 32 + vColB);
                #pragma unroll
                for (int sub = 0; sub < 2; sub++) {
                    const int nt = nn * 2 + sub;
                    mma_f16(O[0][nt], p0, &vhf[sub * 2]);
                    mma_f16(O[1][nt], p1, &vhf[sub * 2]);
                }
            }
        }
    }

    // ---- epilogue: O/l -> fp16, [B,T,D] layout
    #pragma unroll
    for (int mt = 0; mt < 2; mt++) {
        const float inv0 = 1.f / ls[mt * 2], inv1 = 1.f / ls[mt * 2 + 1];
        const size_t a0 = ((size_t)b * NT + gq[mt * 2])     * ND + h * NHD + 2 * (l & 3);
        const size_t a1 = ((size_t)b * NT + gq[mt * 2 + 1]) * ND + h * NHD + 2 * (l & 3);
        #pragma unroll
        for (int nt = 0; nt < 8; nt++) {
            *reinterpret_cast<uint32_t*>(outp + a0 + nt * 8) =
                packh(O[mt][nt][0] * inv0, O[mt][nt][1] * inv0);
            *reinterpret_cast<uint32_t*>(outp + a1 + nt * 8) =
                packh(O[mt][nt][2] * inv1, O[mt][nt][3] * inv1);
        }
    }
}

// ---------------------------------------------------------------------------
extern "C" void kernel_launch(void* const* d_in, const int* in_sizes, int n_in,
                              void* d_out, int out_size)
{
    const float* x     = (const float*)d_in[0];
    const float* eb    = (const float*)d_in[1];
    const float* Wqkv  = (const float*)d_in[2];
    const float* bqkv  = (const float*)d_in[3];
    const float* Wout  = (const float*)d_in[4];
    const float* bout  = (const float*)d_in[5];
    float* out = (float*)d_out;

    __half *xh, *wqh, *woh, *ath, *qh, *kh, *vh;
    __nv_bfloat16* ebbf;
    cudaGetSymbolAddress((void**)&xh,  g_x_h);
    cudaGetSymbolAddress((void**)&wqh, g_wq_h);
    cudaGetSymbolAddress((void**)&woh, g_wo_h);
    cudaGetSymbolAddress((void**)&ath, g_att_h);
    cudaGetSymbolAddress((void**)&qh,  g_q_h);
    cudaGetSymbolAddress((void**)&kh,  g_k_h);
    cudaGetSymbolAddress((void**)&vh,  g_v_h);
    cudaGetSymbolAddress((void**)&ebbf, g_eb_bf);

    const int M = NB * NT;   // 8192

    // [0] fused prepass
    prepass_kernel<<<BLK_SPLIT + BLK_TQKV + BLK_TWO, 256>>>(x, Wqkv, Wout, xh, wqh, woh);

    // [1] bias -> bf16 (pre-scaled by log2e)
    bias_to_bf16_kernel<<<(int)(((size_t)NB * NT * NT) / 4 / 256), 256>>>(eb, ebbf);

    const int gemm_smem = 3 * STG_BYTES;   // 61440 -> 2 CTAs/SM
    cudaFuncSetAttribute(gemm_f16<0>, cudaFuncAttributeMaxDynamicSharedMemorySize, gemm_smem);
    cudaFuncSetAttribute(gemm_f16<1>, cudaFuncAttributeMaxDynamicSharedMemorySize, gemm_smem);

    // [2] QKV projection (1-pass fp16), fused per-head split epilogue
    gemm_f16<1><<<dim3(3 * ND / 128, M / 128), 256, gemm_smem>>>(
        xh, wqh, bqkv, nullptr, qh, kh, vh, M, 3 * ND, ND);

    // [3] flash attention (fp16)  <-- ncu profile index 3
    cudaFuncSetAttribute(flash_mma, cudaFuncAttributeMaxDynamicSharedMemorySize, FLASH_SMEM);
    flash_mma<<<dim3(NT / 128, NH, NB), 128, FLASH_SMEM>>>(qh, kh, vh, ebbf, ath);

    // [4] output projection (1-pass fp16, fp32 out + bias)
    gemm_f16<0><<<dim3(ND / 128, M / 128), 256, gemm_smem>>>(
        ath, woh, bout, out, nullptr, nullptr, nullptr, M, ND, ND);
}